// round 11
// baseline (speedup 1.0000x reference)
#include <cuda_runtime.h>
#include <cuda_bf16.h>
#include <cuda_fp16.h>
#include <math.h>
#include <stdint.h>

// Problem constants
#define T_      8
#define N_      64
#define HW_     256
#define HID_    128
#define NA_     128
#define HX_     514
#define PASS_   258
#define ROWS_   512
#define OUT1_   263168
#define OUTT_   296064

typedef unsigned long long ull;

// ------------------------- scratch (device globals; no allocs) -------------
__device__ float g_gi[HW_ * 384];
__device__ __nv_bfloat16 g_Kh[HW_ * HID_];
__device__ __nv_bfloat16 g_Kl[HW_ * HID_];
__device__ __nv_bfloat16 g_Xh[HW_ * NA_ * HID_];   // X = A+S, bf16 hi/lo
__device__ __nv_bfloat16 g_Xl[HW_ * NA_ * HID_];
__device__ __nv_bfloat16 g_Y1h[HW_ * NA_ * HID_];
__device__ __nv_bfloat16 g_Y1l[HW_ * NA_ * HID_];
__device__ __nv_bfloat16 g_Y2h[HW_ * NA_ * HID_];
__device__ __nv_bfloat16 g_Y2l[HW_ * NA_ * HID_];
__device__ __nv_bfloat16 g_W1h[HID_ * HID_];
__device__ __nv_bfloat16 g_W1l[HID_ * HID_];
__device__ __nv_bfloat16 g_W2h[HID_ * HID_];
__device__ __nv_bfloat16 g_W2l[HID_ * HID_];
__device__ float g_P[(size_t)HW_ * NA_ * HW_];    // logits, layout [w][a][s] fp32
__device__ __half g_Pt[(size_t)HW_ * NA_ * HW_];  // [w][a][s] fp16
__device__ float g_R[ROWS_ * HW_];
__device__ float g_V[ROWS_ * HW_];                // fp32 values
__device__ __half g_Wq[ROWS_ * HW_];              // fp16 centered values
__device__ float g_mu[ROWS_];                     // per-row mean
__device__ int g_cnt[15][4];                      // per-iter, per-mtile arrival counters

// ------------------------- ptx helpers -------------------------------------
__device__ __forceinline__ void fma2(ull& d, ull a, ull b) {
    asm("fma.rn.f32x2 %0, %1, %2, %0;" : "+l"(d) : "l"(a), "l"(b));
}
__device__ __forceinline__ float2 unpack2(ull u) {
    float2 f;
    asm("mov.b64 {%0, %1}, %2;" : "=f"(f.x), "=f"(f.y) : "l"(u));
    return f;
}
__device__ __forceinline__ ull pack2(float x, float y) {
    ull u;
    asm("mov.b64 %0, {%1, %2};" : "=l"(u) : "f"(x), "f"(y));
    return u;
}
__device__ __forceinline__ uint32_t smem_u32(const void* p) {
    uint32_t a;
    asm("{ .reg .u64 t; cvta.to.shared.u64 t, %1; cvt.u32.u64 %0, t; }" : "=r"(a) : "l"(p));
    return a;
}
__device__ __forceinline__ void cp_async16(uint32_t dst, const void* src) {
    asm volatile("cp.async.cg.shared.global [%0], [%1], 16;" ::"r"(dst), "l"(src) : "memory");
}
#define CP_COMMIT() asm volatile("cp.async.commit_group;" ::: "memory")

__device__ __forceinline__ void ldsm_x4(uint32_t* r, uint32_t addr) {
    asm volatile("ldmatrix.sync.aligned.m8n8.x4.shared.b16 {%0,%1,%2,%3}, [%4];"
                 : "=r"(r[0]), "=r"(r[1]), "=r"(r[2]), "=r"(r[3]) : "r"(addr));
}
__device__ __forceinline__ void mma16816(float* c, const uint32_t* a, const uint32_t* b) {
    asm volatile(
        "mma.sync.aligned.m16n8k16.row.col.f32.bf16.bf16.f32 "
        "{%0,%1,%2,%3}, {%4,%5,%6,%7}, {%8,%9}, {%0,%1,%2,%3};"
        : "+f"(c[0]), "+f"(c[1]), "+f"(c[2]), "+f"(c[3])
        : "r"(a[0]), "r"(a[1]), "r"(a[2]), "r"(a[3]), "r"(b[0]), "r"(b[1]));
}
__device__ __forceinline__ void mma16816h(float* c, const uint32_t* a, const uint32_t* b) {
    asm volatile(
        "mma.sync.aligned.m16n8k16.row.col.f32.f16.f16.f32 "
        "{%0,%1,%2,%3}, {%4,%5,%6,%7}, {%8,%9}, {%0,%1,%2,%3};"
        : "+f"(c[0]), "+f"(c[1]), "+f"(c[2]), "+f"(c[3])
        : "r"(a[0]), "r"(a[1]), "r"(a[2]), "r"(a[3]), "r"(b[0]), "r"(b[1]));
}

// swizzled 16KB tile: 128 rows x 128B, seg16 c in 0..7: addr = r*128 + ((c ^ (r&7))<<4)
#define TILE16 16384
__device__ __forceinline__ uint32_t sw_addr(uint32_t base, int r, int c16) {
    return base + r * 128 + (((uint32_t)(c16 ^ (r & 7))) << 4);
}
// bf16 tile loader: 128 rows x 64 elems, stride in elements
__device__ __forceinline__ void load_tile_sw(uint32_t dst, const __nv_bfloat16* src, int stride,
                                             int tid) {
#pragma unroll
    for (int i = 0; i < 4; ++i) {
        int lin = tid + i * 256;
        int r = lin >> 3, seg = lin & 7;
        cp_async16(sw_addr(dst, r, seg), src + (size_t)r * stride + seg * 8);
    }
}
// generic byte-based tile loader: 128 rows x 128B per row from rowBytes-strided src
__device__ __forceinline__ void load_tile_g(uint32_t dst, const void* src, int rowBytes, int tid) {
    const char* s = (const char*)src;
#pragma unroll
    for (int i = 0; i < 4; ++i) {
        int lin = tid + i * 256;
        int r = lin >> 3, seg = lin & 7;
        cp_async16(sw_addr(dst, r, seg), s + (size_t)r * rowBytes + seg * 16);
    }
}

// ------------------------- K1: gi ------------------------------------------
__global__ void gi_kernel(const float* __restrict__ S, const float* __restrict__ w_ih,
                          const float* __restrict__ b_ih) {
    __shared__ float Ss[HID_];
    int blk = blockIdx.x;
    int o = threadIdx.x;
    if (o < HID_) Ss[o] = S[blk * HID_ + o];
    __syncthreads();
    float acc = b_ih[o];
#pragma unroll 8
    for (int k = 0; k < HID_; k += 4) {
        float4 w = *reinterpret_cast<const float4*>(&w_ih[o * HID_ + k]);
        acc += Ss[k] * w.x + Ss[k + 1] * w.y + Ss[k + 2] * w.z + Ss[k + 3] * w.w;
    }
    g_gi[blk * 384 + o] = acc;
}

// ------------------------- K2: GRU (register weights, ILP4) ----------------
__global__ __launch_bounds__(384, 1) void gru_kernel(const float* __restrict__ w_hh,
                                                     const float* __restrict__ b_hh) {
    __shared__ __align__(16) float hs[HID_];
    __shared__ float ghs[384];
    int o = threadIdx.x;

    ull w2[64];
#pragma unroll
    for (int i = 0; i < 64; ++i) {
        float2 v = reinterpret_cast<const float2*>(w_hh)[o * 64 + i];
        w2[i] = pack2(v.x, v.y);
    }
    if (o < HID_) hs[o] = 0.0f;
    float bh = b_hh[o];
    __syncthreads();

    for (int t = 0; t < HW_; ++t) {
        ull z = pack2(0.0f, 0.0f);
        ull a0 = pack2(bh, 0.0f), a1 = z, a2 = z, a3 = z;
        const ull* h2 = reinterpret_cast<const ull*>(hs);
#pragma unroll
        for (int i = 0; i < 64; i += 4) {
            fma2(a0, h2[i], w2[i]);
            fma2(a1, h2[i + 1], w2[i + 1]);
            fma2(a2, h2[i + 2], w2[i + 2]);
            fma2(a3, h2[i + 3], w2[i + 3]);
        }
        float2 p0 = unpack2(a0), p1 = unpack2(a1), p2 = unpack2(a2), p3 = unpack2(a3);
        ghs[o] = (p0.x + p0.y) + (p1.x + p1.y) + ((p2.x + p2.y) + (p3.x + p3.y));
        __syncthreads();
        if (o < HID_) {
            float gir = g_gi[t * 384 + o];
            float giz = g_gi[t * 384 + 128 + o];
            float gin = g_gi[t * 384 + 256 + o];
            float r = 1.0f / (1.0f + expf(-(gir + ghs[o])));
            float zz = 1.0f / (1.0f + expf(-(giz + ghs[o + 128])));
            float n = tanhf(gin + r * ghs[o + 256]);
            float hn = (1.0f - zz) * n + zz * hs[o];
            hs[o] = hn;
            __nv_bfloat16 hi = __float2bfloat16(hn);
            g_Kh[t * HID_ + o] = hi;
            g_Kl[t * HID_ + o] = __float2bfloat16(hn - __bfloat162float(hi));
        }
        __syncthreads();
    }
}

// ------------------------- K3a: split W1, W2 -------------------------------
__global__ void wsplit_kernel(const float* __restrict__ W1, const float* __restrict__ W2) {
    const float* src = blockIdx.x ? W2 : W1;
    __nv_bfloat16* dh = blockIdx.x ? g_W2h : g_W1h;
    __nv_bfloat16* dl = blockIdx.x ? g_W2l : g_W1l;
    for (int i = threadIdx.x; i < HID_ * HID_; i += blockDim.x) {
        float v = src[i];
        __nv_bfloat16 hi = __float2bfloat16(v);
        dh[i] = hi;
        dl[i] = __float2bfloat16(v - __bfloat162float(hi));
    }
}

// ------------------------- K3b: X = A + S, bf16 split ----------------------
// grid (256 w, 8 a-blocks), 256 thr; thread handles 8 k's of one (w,a) row
__global__ __launch_bounds__(256) void xprep_kernel(const float* __restrict__ A,
                                                    const float* __restrict__ S) {
    int w = blockIdx.x, ab = blockIdx.y;
    int al = threadIdx.x >> 4, k8 = (threadIdx.x & 15) * 8;
    int a = ab * 16 + al;
    float4 a0 = *reinterpret_cast<const float4*>(&A[a * HID_ + k8]);
    float4 a1 = *reinterpret_cast<const float4*>(&A[a * HID_ + k8 + 4]);
    float4 s0 = *reinterpret_cast<const float4*>(&S[w * HID_ + k8]);
    float4 s1 = *reinterpret_cast<const float4*>(&S[w * HID_ + k8 + 4]);
    float v[8] = {a0.x + s0.x, a0.y + s0.y, a0.z + s0.z, a0.w + s0.w,
                  a1.x + s1.x, a1.y + s1.y, a1.z + s1.z, a1.w + s1.w};
    __nv_bfloat16 h8[8], l8[8];
#pragma unroll
    for (int i = 0; i < 8; ++i) {
        h8[i] = __float2bfloat16(v[i]);
        l8[i] = __float2bfloat16(v[i] - __bfloat162float(h8[i]));
    }
    size_t off = ((size_t)w * NA_ + a) * HID_ + k8;
    *reinterpret_cast<uint4*>(&g_Xh[off]) = *reinterpret_cast<uint4*>(h8);
    *reinterpret_cast<uint4*>(&g_Xl[off]) = *reinterpret_cast<uint4*>(l8);
}

// ------------------------- K4: unified MLP layer via mma (bf16 3-prod) -----
// layer 0: Y1 = relu(X @ W1^T + b1); layer 1: Y2 = relu(Y1 @ W2^T + b2)
__global__ __launch_bounds__(256, 1) void mlp_mma(int layer, const float* __restrict__ bias) {
    extern __shared__ char smem[];
    uint32_t sb = smem_u32(smem);
    int tid = threadIdx.x, wid = tid >> 5, lane = tid & 31;
    int rt = blockIdx.x;
    int wr = wid >> 1, wc = wid & 1;

    const __nv_bfloat16* xh = layer ? g_Y1h : g_Xh;
    const __nv_bfloat16* xl = layer ? g_Y1l : g_Xl;
    const __nv_bfloat16* wh = layer ? g_W2h : g_W1h;
    const __nv_bfloat16* wl = layer ? g_W2l : g_W1l;
    __nv_bfloat16* dh = layer ? g_Y2h : g_Y1h;
    __nv_bfloat16* dl = layer ? g_Y2l : g_Y1l;

#pragma unroll
    for (int c = 0; c < 2; ++c) {
        load_tile_sw(sb + (0 * 2 + c) * TILE16, xh + (size_t)rt * 16384 + c * 64, 128, tid);
        load_tile_sw(sb + (1 * 2 + c) * TILE16, xl + (size_t)rt * 16384 + c * 64, 128, tid);
        load_tile_sw(sb + (2 * 2 + c) * TILE16, wh + c * 64, 128, tid);
        load_tile_sw(sb + (3 * 2 + c) * TILE16, wl + c * 64, 128, tid);
    }
    CP_COMMIT();
    asm volatile("cp.async.wait_group 0;" ::: "memory");
    __syncthreads();

    float acc[2][8][4];
#pragma unroll
    for (int mb = 0; mb < 2; ++mb)
#pragma unroll
        for (int nt = 0; nt < 8; ++nt)
#pragma unroll
            for (int q = 0; q < 4; ++q) acc[mb][nt][q] = 0.0f;

#pragma unroll
    for (int c = 0; c < 2; ++c) {
        uint32_t ahT = sb + c * TILE16, alT = sb + (2 + c) * TILE16;
        uint32_t bhT = sb + (4 + c) * TILE16, blT = sb + (6 + c) * TILE16;
#pragma unroll
        for (int kk = 0; kk < 4; ++kk) {
            uint32_t ah[2][4], al[2][4];
#pragma unroll
            for (int mb = 0; mb < 2; ++mb) {
                int r = wr * 32 + mb * 16 + (lane & 15);
                int c16 = (lane >> 4) + kk * 2;
                ldsm_x4(ah[mb], sw_addr(ahT, r, c16));
                ldsm_x4(al[mb], sw_addr(alT, r, c16));
            }
            uint32_t bh[8][2], bl[8][2];
#pragma unroll
            for (int np = 0; np < 4; ++np) {
                int n = wc * 64 + np * 16 + ((lane >> 4) << 3) + (lane & 7);
                int c16 = ((lane >> 3) & 1) + kk * 2;
                uint32_t r4[4];
                ldsm_x4(r4, sw_addr(bhT, n, c16));
                bh[np * 2][0] = r4[0]; bh[np * 2][1] = r4[1];
                bh[np * 2 + 1][0] = r4[2]; bh[np * 2 + 1][1] = r4[3];
                ldsm_x4(r4, sw_addr(blT, n, c16));
                bl[np * 2][0] = r4[0]; bl[np * 2][1] = r4[1];
                bl[np * 2 + 1][0] = r4[2]; bl[np * 2 + 1][1] = r4[3];
            }
#pragma unroll
            for (int mb = 0; mb < 2; ++mb)
#pragma unroll
                for (int nt = 0; nt < 8; ++nt) {
                    mma16816(acc[mb][nt], ah[mb], bh[nt]);
                    mma16816(acc[mb][nt], ah[mb], bl[nt]);
                    mma16816(acc[mb][nt], al[mb], bh[nt]);
                }
        }
    }
    int g = lane >> 2;
#pragma unroll
    for (int mb = 0; mb < 2; ++mb)
#pragma unroll
        for (int nt = 0; nt < 8; ++nt) {
            int col = wc * 64 + nt * 8 + (lane & 3) * 2;
            float bb0 = bias[col], bb1 = bias[col + 1];
#pragma unroll
            for (int h = 0; h < 2; ++h) {
                int row = rt * 128 + wr * 32 + mb * 16 + g + h * 8;
                float o0 = fmaxf(acc[mb][nt][2 * h] + bb0, 0.0f);
                float o1 = fmaxf(acc[mb][nt][2 * h + 1] + bb1, 0.0f);
                __nv_bfloat16 h0 = __float2bfloat16(o0);
                __nv_bfloat16 h1 = __float2bfloat16(o1);
                __nv_bfloat162 hp, lp;
                hp.x = h0; hp.y = h1;
                lp.x = __float2bfloat16(o0 - __bfloat162float(h0));
                lp.y = __float2bfloat16(o1 - __bfloat162float(h1));
                *reinterpret_cast<__nv_bfloat162*>(&dh[(size_t)row * HID_ + col]) = hp;
                *reinterpret_cast<__nv_bfloat162*>(&dl[(size_t)row * HID_ + col]) = lp;
            }
        }
}

// ------------------------- K5: logits via mma.sync, writes [w][a][s] -------
__global__ __launch_bounds__(256, 1) void logits_mma() {
    extern __shared__ char smem[];
    uint32_t sb = smem_u32(smem);
    int tid = threadIdx.x, wid = tid >> 5, lane = tid & 31;
    int s0 = blockIdx.x * 128;
    int w = blockIdx.y;
    int wr = wid >> 1, wc = wid & 1;

#pragma unroll
    for (int c = 0; c < 2; ++c) {
        load_tile_sw(sb + (0 * 2 + c) * TILE16, g_Kh + (size_t)s0 * 128 + c * 64, 128, tid);
        load_tile_sw(sb + (1 * 2 + c) * TILE16, g_Kl + (size_t)s0 * 128 + c * 64, 128, tid);
        load_tile_sw(sb + (2 * 2 + c) * TILE16, g_Y2h + (size_t)w * 128 * 128 + c * 64, 128, tid);
        load_tile_sw(sb + (3 * 2 + c) * TILE16, g_Y2l + (size_t)w * 128 * 128 + c * 64, 128, tid);
    }
    CP_COMMIT();
    asm volatile("cp.async.wait_group 0;" ::: "memory");
    __syncthreads();

    float acc[2][8][4];
#pragma unroll
    for (int mb = 0; mb < 2; ++mb)
#pragma unroll
        for (int nt = 0; nt < 8; ++nt)
#pragma unroll
            for (int q = 0; q < 4; ++q) acc[mb][nt][q] = 0.0f;

#pragma unroll
    for (int c = 0; c < 2; ++c) {
        uint32_t ahT = sb + c * TILE16, alT = sb + (2 + c) * TILE16;
        uint32_t bhT = sb + (4 + c) * TILE16, blT = sb + (6 + c) * TILE16;
#pragma unroll
        for (int kk = 0; kk < 4; ++kk) {
            uint32_t ah[2][4], al[2][4];
#pragma unroll
            for (int mb = 0; mb < 2; ++mb) {
                int r = wr * 32 + mb * 16 + (lane & 15);
                int c16 = (lane >> 4) + kk * 2;
                ldsm_x4(ah[mb], sw_addr(ahT, r, c16));
                ldsm_x4(al[mb], sw_addr(alT, r, c16));
            }
            uint32_t bh[8][2], bl[8][2];
#pragma unroll
            for (int np = 0; np < 4; ++np) {
                int n = wc * 64 + np * 16 + ((lane >> 4) << 3) + (lane & 7);
                int c16 = ((lane >> 3) & 1) + kk * 2;
                uint32_t r4[4];
                ldsm_x4(r4, sw_addr(bhT, n, c16));
                bh[np * 2][0] = r4[0]; bh[np * 2][1] = r4[1];
                bh[np * 2 + 1][0] = r4[2]; bh[np * 2 + 1][1] = r4[3];
                ldsm_x4(r4, sw_addr(blT, n, c16));
                bl[np * 2][0] = r4[0]; bl[np * 2][1] = r4[1];
                bl[np * 2 + 1][0] = r4[2]; bl[np * 2 + 1][1] = r4[3];
            }
#pragma unroll
            for (int mb = 0; mb < 2; ++mb)
#pragma unroll
                for (int nt = 0; nt < 8; ++nt) {
                    mma16816(acc[mb][nt], ah[mb], bh[nt]);
                    mma16816(acc[mb][nt], ah[mb], bl[nt]);
                    mma16816(acc[mb][nt], al[mb], bh[nt]);
                }
        }
    }
    // transposed store: L[w][a=col][s=s0+row]
    int g = lane >> 2;
#pragma unroll
    for (int mb = 0; mb < 2; ++mb)
#pragma unroll
        for (int nt = 0; nt < 8; ++nt) {
            int row = wr * 32 + mb * 16 + g;
            int col = wc * 64 + nt * 8 + (lane & 3) * 2;
            size_t b0 = ((size_t)w * NA_ + col) * HW_ + s0 + row;
            g_P[b0] = acc[mb][nt][0];
            g_P[b0 + HW_] = acc[mb][nt][1];
            g_P[b0 + 8] = acc[mb][nt][2];
            g_P[b0 + HW_ + 8] = acc[mb][nt][3];
        }
}

// ------------------------- K6: row softmax over s + fp16 out ---------------
__global__ __launch_bounds__(256) void softmax_rows() {
    int wid = threadIdx.x >> 5, lane = threadIdx.x & 31;
    size_t row = (size_t)blockIdx.x * 8 + wid;  // 0..32767
    const float* base = g_P + row * HW_;
    float4 a = *reinterpret_cast<const float4*>(base + lane * 8);
    float4 b = *reinterpret_cast<const float4*>(base + lane * 8 + 4);
    float m = fmaxf(fmaxf(fmaxf(a.x, a.y), fmaxf(a.z, a.w)),
                    fmaxf(fmaxf(b.x, b.y), fmaxf(b.z, b.w)));
#pragma unroll
    for (int o = 16; o; o >>= 1) m = fmaxf(m, __shfl_xor_sync(0xffffffffu, m, o));
    float e[8];
    e[0] = expf(a.x - m); e[1] = expf(a.y - m); e[2] = expf(a.z - m); e[3] = expf(a.w - m);
    e[4] = expf(b.x - m); e[5] = expf(b.y - m); e[6] = expf(b.z - m); e[7] = expf(b.w - m);
    float s = ((e[0] + e[1]) + (e[2] + e[3])) + ((e[4] + e[5]) + (e[6] + e[7]));
#pragma unroll
    for (int o = 16; o; o >>= 1) s += __shfl_xor_sync(0xffffffffu, s, o);
    float inv = 1.0f / s;
    __half h8[8];
#pragma unroll
    for (int i = 0; i < 8; ++i) h8[i] = __float2half(e[i] * inv);
    *reinterpret_cast<uint4*>(g_Pt + row * HW_ + lane * 8) = *reinterpret_cast<uint4*>(h8);
}

// ------------------------- K7: rewards + V0 init + center/split + counters -
__global__ __launch_bounds__(256) void init_kernel(const float* __restrict__ inputs) {
    __shared__ float part[8];
    int row = blockIdx.x, t = threadIdx.x;
    int wid = t >> 5, lane = t & 31;
    if (row == 0 && t < 60) reinterpret_cast<int*>(g_cnt)[t] = 0;
    float v = inputs[row * 257 + t];
    g_R[row * HW_ + t] = v;
    g_V[row * HW_ + t] = v;
    float s = v;
#pragma unroll
    for (int o = 16; o; o >>= 1) s += __shfl_xor_sync(0xffffffffu, s, o);
    if (lane == 0) part[wid] = s;
    __syncthreads();
    float tot = ((part[0] + part[1]) + (part[2] + part[3])) +
                ((part[4] + part[5]) + (part[6] + part[7]));
    float mu = tot * (1.0f / 256.0f);
    g_Wq[row * HW_ + t] = __float2half(v - mu);
    if (t == 0) g_mu[row] = mu;
}

// ------------------------- K8: Bellman + fused vsplit ----------------------
#define POFF_   65536
#define BSMEM_  98304

__global__ __launch_bounds__(256, 1) void bellman_h(int it) {
    extern __shared__ char smem[];
    __shared__ float red_s[8][32];
    __shared__ int s_doer;
    uint32_t sb = smem_u32(smem);
    int tid = threadIdx.x, wid = tid >> 5, lane = tid & 31;
    int rb = blockIdx.x * 128;
    int w = blockIdx.y;
    int wr = wid >> 1, wc = wid & 1;

    const char* wsrc = (const char*)(g_Wq + (size_t)rb * 256);
    const char* pbase = (const char*)g_Pt + (size_t)w * 65536;

#pragma unroll
    for (int c = 0; c < 4; ++c) load_tile_g(sb + c * TILE16, wsrc + c * 128, 512, tid);
    load_tile_g(sb + POFF_, pbase, 512, tid);
    CP_COMMIT();
    load_tile_g(sb + POFF_ + TILE16, pbase + 128, 512, tid);
    CP_COMMIT();

    float acc[2][8][4];
#pragma unroll
    for (int mb = 0; mb < 2; ++mb)
#pragma unroll
        for (int nt = 0; nt < 8; ++nt)
#pragma unroll
            for (int q = 0; q < 4; ++q) acc[mb][nt][q] = 0.0f;

#pragma unroll
    for (int i = 0; i < 4; ++i) {
        if (i < 3)
            asm volatile("cp.async.wait_group 1;" ::: "memory");
        else
            asm volatile("cp.async.wait_group 0;" ::: "memory");
        __syncthreads();

        uint32_t vT = sb + i * TILE16;
        uint32_t pT = sb + POFF_ + (i & 1) * TILE16;

#pragma unroll
        for (int kk = 0; kk < 4; ++kk) {
            uint32_t ah[2][4];
#pragma unroll
            for (int mb = 0; mb < 2; ++mb) {
                int r = wr * 32 + mb * 16 + (lane & 15);
                int c16 = (lane >> 4) + kk * 2;
                ldsm_x4(ah[mb], sw_addr(vT, r, c16));
            }
            uint32_t bh[8][2];
#pragma unroll
            for (int np = 0; np < 4; ++np) {
                int n = wc * 64 + np * 16 + ((lane >> 4) << 3) + (lane & 7);
                int c16 = ((lane >> 3) & 1) + kk * 2;
                uint32_t r4[4];
                ldsm_x4(r4, sw_addr(pT, n, c16));
                bh[np * 2][0] = r4[0]; bh[np * 2][1] = r4[1];
                bh[np * 2 + 1][0] = r4[2]; bh[np * 2 + 1][1] = r4[3];
            }
#pragma unroll
            for (int mb = 0; mb < 2; ++mb)
#pragma unroll
                for (int nt = 0; nt < 8; ++nt) mma16816h(acc[mb][nt], ah[mb], bh[nt]);
        }
        __syncthreads();

        if (i < 2) {
            load_tile_g(sb + POFF_ + (i & 1) * TILE16, pbase + (i + 2) * 128, 512, tid);
            CP_COMMIT();
        }
    }

    int g = lane >> 2;
#pragma unroll
    for (int mb = 0; mb < 2; ++mb) {
        float mA = -1e30f, mB = -1e30f;
#pragma unroll
        for (int nt = 0; nt < 8; ++nt) {
            mA = fmaxf(mA, fmaxf(acc[mb][nt][0], acc[mb][nt][1]));
            mB = fmaxf(mB, fmaxf(acc[mb][nt][2], acc[mb][nt][3]));
        }
        mA = fmaxf(mA, __shfl_xor_sync(0xffffffffu, mA, 1));
        mA = fmaxf(mA, __shfl_xor_sync(0xffffffffu, mA, 2));
        mB = fmaxf(mB, __shfl_xor_sync(0xffffffffu, mB, 1));
        mB = fmaxf(mB, __shfl_xor_sync(0xffffffffu, mB, 2));
        if ((lane & 3) == 0) {
            red_s[wid][mb * 16 + g] = mA;
            red_s[wid][mb * 16 + 8 + g] = mB;
        }
    }
    __syncthreads();
    if (tid < 128) {
        int wrr = tid >> 5, rl = tid & 31;
        float m = fmaxf(red_s[wrr * 2][rl], red_s[wrr * 2 + 1][rl]);
        int row = rb + tid;
        g_V[row * HW_ + w] = g_R[row * HW_ + w] + m + g_mu[row];
    }

    // fused vsplit: last CTA of this mtile re-centers its 128 rows
    if (it < 14) {
        __syncthreads();
        if (tid == 0) {
            __threadfence();
            int old = atomicAdd(&g_cnt[it][blockIdx.x], 1);
            s_doer = (old == HW_ - 1) ? 1 : 0;
        }
        __syncthreads();
        if (s_doer) {
#pragma unroll
            for (int i = 0; i < 16; ++i) {
                int row = rb + wid * 16 + i;
                const float* v = g_V + row * HW_;
                float4 a = *reinterpret_cast<const float4*>(v + lane * 8);
                float4 b = *reinterpret_cast<const float4*>(v + lane * 8 + 4);
                float s = ((a.x + a.y) + (a.z + a.w)) + ((b.x + b.y) + (b.z + b.w));
#pragma unroll
                for (int o = 16; o; o >>= 1) s += __shfl_xor_sync(0xffffffffu, s, o);
                float mu = s * (1.0f / 256.0f);
                __half h8[8];
                h8[0] = __float2half(a.x - mu);
                h8[1] = __float2half(a.y - mu);
                h8[2] = __float2half(a.z - mu);
                h8[3] = __float2half(a.w - mu);
                h8[4] = __float2half(b.x - mu);
                h8[5] = __float2half(b.y - mu);
                h8[6] = __float2half(b.z - mu);
                h8[7] = __float2half(b.w - mu);
                *reinterpret_cast<uint4*>(g_Wq + row * HW_ + lane * 8) =
                    *reinterpret_cast<uint4*>(h8);
                if (lane == 0) g_mu[row] = mu;
            }
        }
    }
}

// ------------------------- K9: output assembly -----------------------------
__global__ void assemble_kernel(const float* __restrict__ rnn_hxs, float* __restrict__ out,
                                int out_size) {
    int idx = blockIdx.x * blockDim.x + threadIdx.x;
    if (idx >= out_size || idx >= OUTT_) return;
    int row, c;
    if (idx < OUT1_) {
        row = idx / HX_;
        c = idx - row * HX_;
    } else {
        int k = idx - OUT1_;
        int r2 = k / HX_;
        c = k - r2 * HX_;
        row = 448 + r2;
    }
    float v = (c < PASS_) ? rnn_hxs[row * HX_ + c] : g_V[row * HW_ + (c - PASS_)];
    out[idx] = v;
}

// ------------------------- launcher ----------------------------------------
extern "C" void kernel_launch(void* const* d_in, const int* in_sizes, int n_in,
                              void* d_out, int out_size) {
    const float* inputs = (const float*)d_in[0];
    const float* rnn_hxs = (const float*)d_in[1];
    const float* S = (const float*)d_in[2];
    const float* A = (const float*)d_in[3];
    const float* w_ih = (const float*)d_in[4];
    const float* w_hh = (const float*)d_in[5];
    const float* b_ih = (const float*)d_in[6];
    const float* b_hh = (const float*)d_in[7];
    const float* W1 = (const float*)d_in[8];
    const float* b1 = (const float*)d_in[9];
    const float* W2 = (const float*)d_in[10];
    const float* b2 = (const float*)d_in[11];
    float* out = (float*)d_out;

    cudaFuncSetAttribute(bellman_h, cudaFuncAttributeMaxDynamicSharedMemorySize, BSMEM_);
    cudaFuncSetAttribute(logits_mma, cudaFuncAttributeMaxDynamicSharedMemorySize, 131072);
    cudaFuncSetAttribute(mlp_mma, cudaFuncAttributeMaxDynamicSharedMemorySize, 131072);

    gi_kernel<<<HW_, 384>>>(S, w_ih, b_ih);
    gru_kernel<<<1, 384>>>(w_hh, b_hh);
    wsplit_kernel<<<2, 256>>>(W1, W2);
    xprep_kernel<<<dim3(HW_, 8), 256>>>(A, S);
    mlp_mma<<<256, 256, 131072>>>(0, b1);
    mlp_mma<<<256, 256, 131072>>>(1, b2);
    logits_mma<<<dim3(2, HW_), 256, 131072>>>();
    softmax_rows<<<HW_ * NA_ / 8, 256>>>();
    init_kernel<<<ROWS_, 256>>>(inputs);
    for (int it = 0; it < 15; ++it) {
        bellman_h<<<dim3(4, HW_), 256, BSMEM_>>>(it);
    }
    int total = out_size < OUTT_ ? out_size : OUTT_;
    assemble_kernel<<<(total + 255) / 256, 256>>>(rnn_hxs, out, out_size);
}

// round 12
// speedup vs baseline: 1.3719x; 1.3719x over previous
#include <cuda_runtime.h>
#include <cuda_bf16.h>
#include <cuda_fp16.h>
#include <math.h>
#include <stdint.h>

// Problem constants
#define T_      8
#define N_      64
#define HW_     256
#define HID_    128
#define NA_     128
#define HX_     514
#define PASS_   258
#define ROWS_   512
#define OUT1_   263168
#define OUTT_   296064

typedef unsigned long long ull;

// ------------------------- scratch (device globals; no allocs) -------------
__device__ float g_gi[HW_ * 384];
__device__ __nv_bfloat16 g_Kh[HW_ * HID_];
__device__ __nv_bfloat16 g_Kl[HW_ * HID_];
__device__ __nv_bfloat16 g_Xh[HW_ * NA_ * HID_];   // X = A+S, bf16 hi/lo
__device__ __nv_bfloat16 g_Xl[HW_ * NA_ * HID_];
__device__ __nv_bfloat16 g_Y1h[HW_ * NA_ * HID_];
__device__ __nv_bfloat16 g_Y1l[HW_ * NA_ * HID_];
__device__ __nv_bfloat16 g_Y2h[HW_ * NA_ * HID_];
__device__ __nv_bfloat16 g_Y2l[HW_ * NA_ * HID_];
__device__ __nv_bfloat16 g_W1h[HID_ * HID_];
__device__ __nv_bfloat16 g_W1l[HID_ * HID_];
__device__ __nv_bfloat16 g_W2h[HID_ * HID_];
__device__ __nv_bfloat16 g_W2l[HID_ * HID_];
__device__ float g_P[(size_t)HW_ * NA_ * HW_];    // logits, layout [w][a][s] fp32
__device__ __half g_Pt[(size_t)HW_ * NA_ * HW_];  // [w][a][s] fp16
__device__ float g_R[ROWS_ * HW_];
__device__ float g_V[ROWS_ * HW_];                // fp32 values
__device__ __half g_Wq[ROWS_ * HW_];              // fp16 centered values
__device__ float g_mu[ROWS_];                     // per-row mean

// ------------------------- ptx helpers -------------------------------------
__device__ __forceinline__ void fma2(ull& d, ull a, ull b) {
    asm("fma.rn.f32x2 %0, %1, %2, %0;" : "+l"(d) : "l"(a), "l"(b));
}
__device__ __forceinline__ float2 unpack2(ull u) {
    float2 f;
    asm("mov.b64 {%0, %1}, %2;" : "=f"(f.x), "=f"(f.y) : "l"(u));
    return f;
}
__device__ __forceinline__ ull pack2(float x, float y) {
    ull u;
    asm("mov.b64 %0, {%1, %2};" : "=l"(u) : "f"(x), "f"(y));
    return u;
}
__device__ __forceinline__ uint32_t smem_u32(const void* p) {
    uint32_t a;
    asm("{ .reg .u64 t; cvta.to.shared.u64 t, %1; cvt.u32.u64 %0, t; }" : "=r"(a) : "l"(p));
    return a;
}
__device__ __forceinline__ void cp_async16(uint32_t dst, const void* src) {
    asm volatile("cp.async.cg.shared.global [%0], [%1], 16;" ::"r"(dst), "l"(src) : "memory");
}
#define CP_COMMIT() asm volatile("cp.async.commit_group;" ::: "memory")

__device__ __forceinline__ void ldsm_x4(uint32_t* r, uint32_t addr) {
    asm volatile("ldmatrix.sync.aligned.m8n8.x4.shared.b16 {%0,%1,%2,%3}, [%4];"
                 : "=r"(r[0]), "=r"(r[1]), "=r"(r[2]), "=r"(r[3]) : "r"(addr));
}
__device__ __forceinline__ void mma16816(float* c, const uint32_t* a, const uint32_t* b) {
    asm volatile(
        "mma.sync.aligned.m16n8k16.row.col.f32.bf16.bf16.f32 "
        "{%0,%1,%2,%3}, {%4,%5,%6,%7}, {%8,%9}, {%0,%1,%2,%3};"
        : "+f"(c[0]), "+f"(c[1]), "+f"(c[2]), "+f"(c[3])
        : "r"(a[0]), "r"(a[1]), "r"(a[2]), "r"(a[3]), "r"(b[0]), "r"(b[1]));
}
__device__ __forceinline__ void mma16816h(float* c, const uint32_t* a, const uint32_t* b) {
    asm volatile(
        "mma.sync.aligned.m16n8k16.row.col.f32.f16.f16.f32 "
        "{%0,%1,%2,%3}, {%4,%5,%6,%7}, {%8,%9}, {%0,%1,%2,%3};"
        : "+f"(c[0]), "+f"(c[1]), "+f"(c[2]), "+f"(c[3])
        : "r"(a[0]), "r"(a[1]), "r"(a[2]), "r"(a[3]), "r"(b[0]), "r"(b[1]));
}

// swizzled 16KB tile: 128 rows x 128B, seg16 c in 0..7: addr = r*128 + ((c ^ (r&7))<<4)
#define TILE16 16384
__device__ __forceinline__ uint32_t sw_addr(uint32_t base, int r, int c16) {
    return base + r * 128 + (((uint32_t)(c16 ^ (r & 7))) << 4);
}
// bf16 tile loader: 128 rows x 64 elems, stride in elements
__device__ __forceinline__ void load_tile_sw(uint32_t dst, const __nv_bfloat16* src, int stride,
                                             int tid) {
#pragma unroll
    for (int i = 0; i < 4; ++i) {
        int lin = tid + i * 256;
        int r = lin >> 3, seg = lin & 7;
        cp_async16(sw_addr(dst, r, seg), src + (size_t)r * stride + seg * 8);
    }
}
// generic byte-based tile loader: 128 rows x 128B per row from rowBytes-strided src
__device__ __forceinline__ void load_tile_g(uint32_t dst, const void* src, int rowBytes, int tid) {
    const char* s = (const char*)src;
#pragma unroll
    for (int i = 0; i < 4; ++i) {
        int lin = tid + i * 256;
        int r = lin >> 3, seg = lin & 7;
        cp_async16(sw_addr(dst, r, seg), s + (size_t)r * rowBytes + seg * 16);
    }
}

// ------------------------- K1: gi ------------------------------------------
__global__ void gi_kernel(const float* __restrict__ S, const float* __restrict__ w_ih,
                          const float* __restrict__ b_ih) {
    __shared__ float Ss[HID_];
    int blk = blockIdx.x;
    int o = threadIdx.x;
    if (o < HID_) Ss[o] = S[blk * HID_ + o];
    __syncthreads();
    float acc = b_ih[o];
#pragma unroll 8
    for (int k = 0; k < HID_; k += 4) {
        float4 w = *reinterpret_cast<const float4*>(&w_ih[o * HID_ + k]);
        acc += Ss[k] * w.x + Ss[k + 1] * w.y + Ss[k + 2] * w.z + Ss[k + 3] * w.w;
    }
    g_gi[blk * 384 + o] = acc;
}

// ------------------------- K2: GRU (register weights, ILP4) ----------------
__global__ __launch_bounds__(384, 1) void gru_kernel(const float* __restrict__ w_hh,
                                                     const float* __restrict__ b_hh) {
    __shared__ __align__(16) float hs[HID_];
    __shared__ float ghs[384];
    int o = threadIdx.x;

    ull w2[64];
#pragma unroll
    for (int i = 0; i < 64; ++i) {
        float2 v = reinterpret_cast<const float2*>(w_hh)[o * 64 + i];
        w2[i] = pack2(v.x, v.y);
    }
    if (o < HID_) hs[o] = 0.0f;
    float bh = b_hh[o];
    __syncthreads();

    for (int t = 0; t < HW_; ++t) {
        ull z = pack2(0.0f, 0.0f);
        ull a0 = pack2(bh, 0.0f), a1 = z, a2 = z, a3 = z;
        const ull* h2 = reinterpret_cast<const ull*>(hs);
#pragma unroll
        for (int i = 0; i < 64; i += 4) {
            fma2(a0, h2[i], w2[i]);
            fma2(a1, h2[i + 1], w2[i + 1]);
            fma2(a2, h2[i + 2], w2[i + 2]);
            fma2(a3, h2[i + 3], w2[i + 3]);
        }
        float2 p0 = unpack2(a0), p1 = unpack2(a1), p2 = unpack2(a2), p3 = unpack2(a3);
        ghs[o] = (p0.x + p0.y) + (p1.x + p1.y) + ((p2.x + p2.y) + (p3.x + p3.y));
        __syncthreads();
        if (o < HID_) {
            float gir = g_gi[t * 384 + o];
            float giz = g_gi[t * 384 + 128 + o];
            float gin = g_gi[t * 384 + 256 + o];
            float r = 1.0f / (1.0f + expf(-(gir + ghs[o])));
            float zz = 1.0f / (1.0f + expf(-(giz + ghs[o + 128])));
            float n = tanhf(gin + r * ghs[o + 256]);
            float hn = (1.0f - zz) * n + zz * hs[o];
            hs[o] = hn;
            __nv_bfloat16 hi = __float2bfloat16(hn);
            g_Kh[t * HID_ + o] = hi;
            g_Kl[t * HID_ + o] = __float2bfloat16(hn - __bfloat162float(hi));
        }
        __syncthreads();
    }
}

// ------------------------- K3a: split W1, W2 -------------------------------
__global__ void wsplit_kernel(const float* __restrict__ W1, const float* __restrict__ W2) {
    const float* src = blockIdx.x ? W2 : W1;
    __nv_bfloat16* dh = blockIdx.x ? g_W2h : g_W1h;
    __nv_bfloat16* dl = blockIdx.x ? g_W2l : g_W1l;
    for (int i = threadIdx.x; i < HID_ * HID_; i += blockDim.x) {
        float v = src[i];
        __nv_bfloat16 hi = __float2bfloat16(v);
        dh[i] = hi;
        dl[i] = __float2bfloat16(v - __bfloat162float(hi));
    }
}

// ------------------------- K3b: X = A + S, bf16 split ----------------------
__global__ __launch_bounds__(256) void xprep_kernel(const float* __restrict__ A,
                                                    const float* __restrict__ S) {
    int w = blockIdx.x, ab = blockIdx.y;
    int al = threadIdx.x >> 4, k8 = (threadIdx.x & 15) * 8;
    int a = ab * 16 + al;
    float4 a0 = *reinterpret_cast<const float4*>(&A[a * HID_ + k8]);
    float4 a1 = *reinterpret_cast<const float4*>(&A[a * HID_ + k8 + 4]);
    float4 s0 = *reinterpret_cast<const float4*>(&S[w * HID_ + k8]);
    float4 s1 = *reinterpret_cast<const float4*>(&S[w * HID_ + k8 + 4]);
    float v[8] = {a0.x + s0.x, a0.y + s0.y, a0.z + s0.z, a0.w + s0.w,
                  a1.x + s1.x, a1.y + s1.y, a1.z + s1.z, a1.w + s1.w};
    __nv_bfloat16 h8[8], l8[8];
#pragma unroll
    for (int i = 0; i < 8; ++i) {
        h8[i] = __float2bfloat16(v[i]);
        l8[i] = __float2bfloat16(v[i] - __bfloat162float(h8[i]));
    }
    size_t off = ((size_t)w * NA_ + a) * HID_ + k8;
    *reinterpret_cast<uint4*>(&g_Xh[off]) = *reinterpret_cast<uint4*>(h8);
    *reinterpret_cast<uint4*>(&g_Xl[off]) = *reinterpret_cast<uint4*>(l8);
}

// ------------------------- K4: unified MLP layer via mma (bf16 3-prod) -----
__global__ __launch_bounds__(256, 1) void mlp_mma(int layer, const float* __restrict__ bias) {
    extern __shared__ char smem[];
    uint32_t sb = smem_u32(smem);
    int tid = threadIdx.x, wid = tid >> 5, lane = tid & 31;
    int rt = blockIdx.x;
    int wr = wid >> 1, wc = wid & 1;

    const __nv_bfloat16* xh = layer ? g_Y1h : g_Xh;
    const __nv_bfloat16* xl = layer ? g_Y1l : g_Xl;
    const __nv_bfloat16* wh = layer ? g_W2h : g_W1h;
    const __nv_bfloat16* wl = layer ? g_W2l : g_W1l;
    __nv_bfloat16* dh = layer ? g_Y2h : g_Y1h;
    __nv_bfloat16* dl = layer ? g_Y2l : g_Y1l;

#pragma unroll
    for (int c = 0; c < 2; ++c) {
        load_tile_sw(sb + (0 * 2 + c) * TILE16, xh + (size_t)rt * 16384 + c * 64, 128, tid);
        load_tile_sw(sb + (1 * 2 + c) * TILE16, xl + (size_t)rt * 16384 + c * 64, 128, tid);
        load_tile_sw(sb + (2 * 2 + c) * TILE16, wh + c * 64, 128, tid);
        load_tile_sw(sb + (3 * 2 + c) * TILE16, wl + c * 64, 128, tid);
    }
    CP_COMMIT();
    asm volatile("cp.async.wait_group 0;" ::: "memory");
    __syncthreads();

    float acc[2][8][4];
#pragma unroll
    for (int mb = 0; mb < 2; ++mb)
#pragma unroll
        for (int nt = 0; nt < 8; ++nt)
#pragma unroll
            for (int q = 0; q < 4; ++q) acc[mb][nt][q] = 0.0f;

#pragma unroll
    for (int c = 0; c < 2; ++c) {
        uint32_t ahT = sb + c * TILE16, alT = sb + (2 + c) * TILE16;
        uint32_t bhT = sb + (4 + c) * TILE16, blT = sb + (6 + c) * TILE16;
#pragma unroll
        for (int kk = 0; kk < 4; ++kk) {
            uint32_t ah[2][4], al[2][4];
#pragma unroll
            for (int mb = 0; mb < 2; ++mb) {
                int r = wr * 32 + mb * 16 + (lane & 15);
                int c16 = (lane >> 4) + kk * 2;
                ldsm_x4(ah[mb], sw_addr(ahT, r, c16));
                ldsm_x4(al[mb], sw_addr(alT, r, c16));
            }
            uint32_t bh[8][2], bl[8][2];
#pragma unroll
            for (int np = 0; np < 4; ++np) {
                int n = wc * 64 + np * 16 + ((lane >> 4) << 3) + (lane & 7);
                int c16 = ((lane >> 3) & 1) + kk * 2;
                uint32_t r4[4];
                ldsm_x4(r4, sw_addr(bhT, n, c16));
                bh[np * 2][0] = r4[0]; bh[np * 2][1] = r4[1];
                bh[np * 2 + 1][0] = r4[2]; bh[np * 2 + 1][1] = r4[3];
                ldsm_x4(r4, sw_addr(blT, n, c16));
                bl[np * 2][0] = r4[0]; bl[np * 2][1] = r4[1];
                bl[np * 2 + 1][0] = r4[2]; bl[np * 2 + 1][1] = r4[3];
            }
#pragma unroll
            for (int mb = 0; mb < 2; ++mb)
#pragma unroll
                for (int nt = 0; nt < 8; ++nt) {
                    mma16816(acc[mb][nt], ah[mb], bh[nt]);
                    mma16816(acc[mb][nt], ah[mb], bl[nt]);
                    mma16816(acc[mb][nt], al[mb], bh[nt]);
                }
        }
    }
    int g = lane >> 2;
#pragma unroll
    for (int mb = 0; mb < 2; ++mb)
#pragma unroll
        for (int nt = 0; nt < 8; ++nt) {
            int col = wc * 64 + nt * 8 + (lane & 3) * 2;
            float bb0 = bias[col], bb1 = bias[col + 1];
#pragma unroll
            for (int h = 0; h < 2; ++h) {
                int row = rt * 128 + wr * 32 + mb * 16 + g + h * 8;
                float o0 = fmaxf(acc[mb][nt][2 * h] + bb0, 0.0f);
                float o1 = fmaxf(acc[mb][nt][2 * h + 1] + bb1, 0.0f);
                __nv_bfloat16 h0 = __float2bfloat16(o0);
                __nv_bfloat16 h1 = __float2bfloat16(o1);
                __nv_bfloat162 hp, lp;
                hp.x = h0; hp.y = h1;
                lp.x = __float2bfloat16(o0 - __bfloat162float(h0));
                lp.y = __float2bfloat16(o1 - __bfloat162float(h1));
                *reinterpret_cast<__nv_bfloat162*>(&dh[(size_t)row * HID_ + col]) = hp;
                *reinterpret_cast<__nv_bfloat162*>(&dl[(size_t)row * HID_ + col]) = lp;
            }
        }
}

// ------------------------- K5: logits via mma.sync, writes [w][a][s] -------
__global__ __launch_bounds__(256, 1) void logits_mma() {
    extern __shared__ char smem[];
    uint32_t sb = smem_u32(smem);
    int tid = threadIdx.x, wid = tid >> 5, lane = tid & 31;
    int s0 = blockIdx.x * 128;
    int w = blockIdx.y;
    int wr = wid >> 1, wc = wid & 1;

#pragma unroll
    for (int c = 0; c < 2; ++c) {
        load_tile_sw(sb + (0 * 2 + c) * TILE16, g_Kh + (size_t)s0 * 128 + c * 64, 128, tid);
        load_tile_sw(sb + (1 * 2 + c) * TILE16, g_Kl + (size_t)s0 * 128 + c * 64, 128, tid);
        load_tile_sw(sb + (2 * 2 + c) * TILE16, g_Y2h + (size_t)w * 128 * 128 + c * 64, 128, tid);
        load_tile_sw(sb + (3 * 2 + c) * TILE16, g_Y2l + (size_t)w * 128 * 128 + c * 64, 128, tid);
    }
    CP_COMMIT();
    asm volatile("cp.async.wait_group 0;" ::: "memory");
    __syncthreads();

    float acc[2][8][4];
#pragma unroll
    for (int mb = 0; mb < 2; ++mb)
#pragma unroll
        for (int nt = 0; nt < 8; ++nt)
#pragma unroll
            for (int q = 0; q < 4; ++q) acc[mb][nt][q] = 0.0f;

#pragma unroll
    for (int c = 0; c < 2; ++c) {
        uint32_t ahT = sb + c * TILE16, alT = sb + (2 + c) * TILE16;
        uint32_t bhT = sb + (4 + c) * TILE16, blT = sb + (6 + c) * TILE16;
#pragma unroll
        for (int kk = 0; kk < 4; ++kk) {
            uint32_t ah[2][4], al[2][4];
#pragma unroll
            for (int mb = 0; mb < 2; ++mb) {
                int r = wr * 32 + mb * 16 + (lane & 15);
                int c16 = (lane >> 4) + kk * 2;
                ldsm_x4(ah[mb], sw_addr(ahT, r, c16));
                ldsm_x4(al[mb], sw_addr(alT, r, c16));
            }
            uint32_t bh[8][2], bl[8][2];
#pragma unroll
            for (int np = 0; np < 4; ++np) {
                int n = wc * 64 + np * 16 + ((lane >> 4) << 3) + (lane & 7);
                int c16 = ((lane >> 3) & 1) + kk * 2;
                uint32_t r4[4];
                ldsm_x4(r4, sw_addr(bhT, n, c16));
                bh[np * 2][0] = r4[0]; bh[np * 2][1] = r4[1];
                bh[np * 2 + 1][0] = r4[2]; bh[np * 2 + 1][1] = r4[3];
                ldsm_x4(r4, sw_addr(blT, n, c16));
                bl[np * 2][0] = r4[0]; bl[np * 2][1] = r4[1];
                bl[np * 2 + 1][0] = r4[2]; bl[np * 2 + 1][1] = r4[3];
            }
#pragma unroll
            for (int mb = 0; mb < 2; ++mb)
#pragma unroll
                for (int nt = 0; nt < 8; ++nt) {
                    mma16816(acc[mb][nt], ah[mb], bh[nt]);
                    mma16816(acc[mb][nt], ah[mb], bl[nt]);
                    mma16816(acc[mb][nt], al[mb], bh[nt]);
                }
        }
    }
    // transposed store: L[w][a=col][s=s0+row]
    int g = lane >> 2;
#pragma unroll
    for (int mb = 0; mb < 2; ++mb)
#pragma unroll
        for (int nt = 0; nt < 8; ++nt) {
            int row = wr * 32 + mb * 16 + g;
            int col = wc * 64 + nt * 8 + (lane & 3) * 2;
            size_t b0 = ((size_t)w * NA_ + col) * HW_ + s0 + row;
            g_P[b0] = acc[mb][nt][0];
            g_P[b0 + HW_] = acc[mb][nt][1];
            g_P[b0 + 8] = acc[mb][nt][2];
            g_P[b0 + HW_ + 8] = acc[mb][nt][3];
        }
}

// ------------------------- K6: row softmax over s + fp16 out ---------------
__global__ __launch_bounds__(256) void softmax_rows() {
    int wid = threadIdx.x >> 5, lane = threadIdx.x & 31;
    size_t row = (size_t)blockIdx.x * 8 + wid;  // 0..32767
    const float* base = g_P + row * HW_;
    float4 a = *reinterpret_cast<const float4*>(base + lane * 8);
    float4 b = *reinterpret_cast<const float4*>(base + lane * 8 + 4);
    float m = fmaxf(fmaxf(fmaxf(a.x, a.y), fmaxf(a.z, a.w)),
                    fmaxf(fmaxf(b.x, b.y), fmaxf(b.z, b.w)));
#pragma unroll
    for (int o = 16; o; o >>= 1) m = fmaxf(m, __shfl_xor_sync(0xffffffffu, m, o));
    float e[8];
    e[0] = expf(a.x - m); e[1] = expf(a.y - m); e[2] = expf(a.z - m); e[3] = expf(a.w - m);
    e[4] = expf(b.x - m); e[5] = expf(b.y - m); e[6] = expf(b.z - m); e[7] = expf(b.w - m);
    float s = ((e[0] + e[1]) + (e[2] + e[3])) + ((e[4] + e[5]) + (e[6] + e[7]));
#pragma unroll
    for (int o = 16; o; o >>= 1) s += __shfl_xor_sync(0xffffffffu, s, o);
    float inv = 1.0f / s;
    __half h8[8];
#pragma unroll
    for (int i = 0; i < 8; ++i) h8[i] = __float2half(e[i] * inv);
    *reinterpret_cast<uint4*>(g_Pt + row * HW_ + lane * 8) = *reinterpret_cast<uint4*>(h8);
}

// ------------------------- K7: rewards + V0 init + center/split ------------
__global__ __launch_bounds__(256) void init_kernel(const float* __restrict__ inputs) {
    __shared__ float part[8];
    int row = blockIdx.x, t = threadIdx.x;
    int wid = t >> 5, lane = t & 31;
    float v = inputs[row * 257 + t];
    g_R[row * HW_ + t] = v;
    g_V[row * HW_ + t] = v;
    float s = v;
#pragma unroll
    for (int o = 16; o; o >>= 1) s += __shfl_xor_sync(0xffffffffu, s, o);
    if (lane == 0) part[wid] = s;
    __syncthreads();
    float tot = ((part[0] + part[1]) + (part[2] + part[3])) +
                ((part[4] + part[5]) + (part[6] + part[7]));
    float mu = tot * (1.0f / 256.0f);
    g_Wq[row * HW_ + t] = __float2half(v - mu);
    if (t == 0) g_mu[row] = mu;
}

// ------------------------- K7b: center + fp16 split of V -------------------
__global__ __launch_bounds__(256) void vsplit_kernel() {
    int wid = threadIdx.x >> 5, lane = threadIdx.x & 31;
    int row = blockIdx.x * 8 + wid;
    const float* v = g_V + row * HW_;
    float4 a = *reinterpret_cast<const float4*>(v + lane * 8);
    float4 b = *reinterpret_cast<const float4*>(v + lane * 8 + 4);
    float s = ((a.x + a.y) + (a.z + a.w)) + ((b.x + b.y) + (b.z + b.w));
#pragma unroll
    for (int o = 16; o; o >>= 1) s += __shfl_xor_sync(0xffffffffu, s, o);
    float mu = s * (1.0f / 256.0f);
    __half h8[8];
    h8[0] = __float2half(a.x - mu);
    h8[1] = __float2half(a.y - mu);
    h8[2] = __float2half(a.z - mu);
    h8[3] = __float2half(a.w - mu);
    h8[4] = __float2half(b.x - mu);
    h8[5] = __float2half(b.y - mu);
    h8[6] = __float2half(b.z - mu);
    h8[7] = __float2half(b.w - mu);
    *reinterpret_cast<uint4*>(g_Wq + row * HW_ + lane * 8) = *reinterpret_cast<uint4*>(h8);
    if (lane == 0) g_mu[row] = mu;
}

// ------------------------- K8: Bellman via fp16 mma (1 product, centered) --
#define POFF_   65536
#define BSMEM_  98304

__global__ __launch_bounds__(256, 1) void bellman_h() {
    extern __shared__ char smem[];
    __shared__ float red_s[8][32];
    uint32_t sb = smem_u32(smem);
    int tid = threadIdx.x, wid = tid >> 5, lane = tid & 31;
    int rb = blockIdx.x * 128;
    int w = blockIdx.y;
    int wr = wid >> 1, wc = wid & 1;

    const char* wsrc = (const char*)(g_Wq + (size_t)rb * 256);
    const char* pbase = (const char*)g_Pt + (size_t)w * 65536;

#pragma unroll
    for (int c = 0; c < 4; ++c) load_tile_g(sb + c * TILE16, wsrc + c * 128, 512, tid);
    load_tile_g(sb + POFF_, pbase, 512, tid);
    CP_COMMIT();
    load_tile_g(sb + POFF_ + TILE16, pbase + 128, 512, tid);
    CP_COMMIT();

    float acc[2][8][4];
#pragma unroll
    for (int mb = 0; mb < 2; ++mb)
#pragma unroll
        for (int nt = 0; nt < 8; ++nt)
#pragma unroll
            for (int q = 0; q < 4; ++q) acc[mb][nt][q] = 0.0f;

#pragma unroll
    for (int i = 0; i < 4; ++i) {
        if (i < 3)
            asm volatile("cp.async.wait_group 1;" ::: "memory");
        else
            asm volatile("cp.async.wait_group 0;" ::: "memory");
        __syncthreads();

        uint32_t vT = sb + i * TILE16;
        uint32_t pT = sb + POFF_ + (i & 1) * TILE16;

#pragma unroll
        for (int kk = 0; kk < 4; ++kk) {
            uint32_t ah[2][4];
#pragma unroll
            for (int mb = 0; mb < 2; ++mb) {
                int r = wr * 32 + mb * 16 + (lane & 15);
                int c16 = (lane >> 4) + kk * 2;
                ldsm_x4(ah[mb], sw_addr(vT, r, c16));
            }
            uint32_t bh[8][2];
#pragma unroll
            for (int np = 0; np < 4; ++np) {
                int n = wc * 64 + np * 16 + ((lane >> 4) << 3) + (lane & 7);
                int c16 = ((lane >> 3) & 1) + kk * 2;
                uint32_t r4[4];
                ldsm_x4(r4, sw_addr(pT, n, c16));
                bh[np * 2][0] = r4[0]; bh[np * 2][1] = r4[1];
                bh[np * 2 + 1][0] = r4[2]; bh[np * 2 + 1][1] = r4[3];
            }
#pragma unroll
            for (int mb = 0; mb < 2; ++mb)
#pragma unroll
                for (int nt = 0; nt < 8; ++nt) mma16816h(acc[mb][nt], ah[mb], bh[nt]);
        }
        __syncthreads();

        if (i < 2) {
            load_tile_g(sb + POFF_ + (i & 1) * TILE16, pbase + (i + 2) * 128, 512, tid);
            CP_COMMIT();
        }
    }

    int g = lane >> 2;
#pragma unroll
    for (int mb = 0; mb < 2; ++mb) {
        float mA = -1e30f, mB = -1e30f;
#pragma unroll
        for (int nt = 0; nt < 8; ++nt) {
            mA = fmaxf(mA, fmaxf(acc[mb][nt][0], acc[mb][nt][1]));
            mB = fmaxf(mB, fmaxf(acc[mb][nt][2], acc[mb][nt][3]));
        }
        mA = fmaxf(mA, __shfl_xor_sync(0xffffffffu, mA, 1));
        mA = fmaxf(mA, __shfl_xor_sync(0xffffffffu, mA, 2));
        mB = fmaxf(mB, __shfl_xor_sync(0xffffffffu, mB, 1));
        mB = fmaxf(mB, __shfl_xor_sync(0xffffffffu, mB, 2));
        if ((lane & 3) == 0) {
            red_s[wid][mb * 16 + g] = mA;
            red_s[wid][mb * 16 + 8 + g] = mB;
        }
    }
    __syncthreads();
    if (tid < 128) {
        int wrr = tid >> 5, rl = tid & 31;
        float m = fmaxf(red_s[wrr * 2][rl], red_s[wrr * 2 + 1][rl]);
        int row = rb + tid;
        g_V[row * HW_ + w] = g_R[row * HW_ + w] + m + g_mu[row];
    }
}

// ------------------------- K9: output assembly -----------------------------
__global__ void assemble_kernel(const float* __restrict__ rnn_hxs, float* __restrict__ out,
                                int out_size) {
    int idx = blockIdx.x * blockDim.x + threadIdx.x;
    if (idx >= out_size || idx >= OUTT_) return;
    int row, c;
    if (idx < OUT1_) {
        row = idx / HX_;
        c = idx - row * HX_;
    } else {
        int k = idx - OUT1_;
        int r2 = k / HX_;
        c = k - r2 * HX_;
        row = 448 + r2;
    }
    float v = (c < PASS_) ? rnn_hxs[row * HX_ + c] : g_V[row * HW_ + (c - PASS_)];
    out[idx] = v;
}

// ------------------------- launcher ----------------------------------------
extern "C" void kernel_launch(void* const* d_in, const int* in_sizes, int n_in,
                              void* d_out, int out_size) {
    const float* inputs = (const float*)d_in[0];
    const float* rnn_hxs = (const float*)d_in[1];
    const float* S = (const float*)d_in[2];
    const float* A = (const float*)d_in[3];
    const float* w_ih = (const float*)d_in[4];
    const float* w_hh = (const float*)d_in[5];
    const float* b_ih = (const float*)d_in[6];
    const float* b_hh = (const float*)d_in[7];
    const float* W1 = (const float*)d_in[8];
    const float* b1 = (const float*)d_in[9];
    const float* W2 = (const float*)d_in[10];
    const float* b2 = (const float*)d_in[11];
    float* out = (float*)d_out;

    cudaFuncSetAttribute(bellman_h, cudaFuncAttributeMaxDynamicSharedMemorySize, BSMEM_);
    cudaFuncSetAttribute(logits_mma, cudaFuncAttributeMaxDynamicSharedMemorySize, 131072);
    cudaFuncSetAttribute(mlp_mma, cudaFuncAttributeMaxDynamicSharedMemorySize, 131072);

    gi_kernel<<<HW_, 384>>>(S, w_ih, b_ih);
    gru_kernel<<<1, 384>>>(w_hh, b_hh);
    wsplit_kernel<<<2, 256>>>(W1, W2);
    xprep_kernel<<<dim3(HW_, 8), 256>>>(A, S);
    mlp_mma<<<256, 256, 131072>>>(0, b1);
    mlp_mma<<<256, 256, 131072>>>(1, b2);
    logits_mma<<<dim3(2, HW_), 256, 131072>>>();
    softmax_rows<<<HW_ * NA_ / 8, 256>>>();
    init_kernel<<<ROWS_, 256>>>(inputs);
    for (int it = 0; it < 15; ++it) {
        bellman_h<<<dim3(4, HW_), 256, BSMEM_>>>();
        if (it < 14) vsplit_kernel<<<ROWS_ / 8, 256>>>();
    }
    int total = out_size < OUTT_ ? out_size : OUTT_;
    assemble_kernel<<<(total + 255) / 256, 256>>>(rnn_hxs, out, out_size);
}

// round 14
// speedup vs baseline: 1.4502x; 1.0571x over previous
#include <cuda_runtime.h>
#include <cuda_bf16.h>
#include <cuda_fp16.h>
#include <math.h>
#include <stdint.h>

// Problem constants
#define T_      8
#define N_      64
#define HW_     256
#define HID_    128
#define NA_     128
#define HX_     514
#define PASS_   258
#define ROWS_   512
#define OUT1_   263168
#define OUTT_   296064

typedef unsigned long long ull;

// ------------------------- scratch (device globals; no allocs) -------------
__device__ float g_gi[HW_ * 384];
__device__ __nv_bfloat16 g_Kh[HW_ * HID_];
__device__ __nv_bfloat16 g_Kl[HW_ * HID_];
__device__ __nv_bfloat16 g_Xh[HW_ * NA_ * HID_];   // X = A+S, bf16 hi/lo
__device__ __nv_bfloat16 g_Xl[HW_ * NA_ * HID_];
__device__ __nv_bfloat16 g_Y1h[HW_ * NA_ * HID_];
__device__ __nv_bfloat16 g_Y1l[HW_ * NA_ * HID_];
__device__ __nv_bfloat16 g_Y2h[HW_ * NA_ * HID_];
__device__ __nv_bfloat16 g_Y2l[HW_ * NA_ * HID_];
__device__ __nv_bfloat16 g_W1h[HID_ * HID_];
__device__ __nv_bfloat16 g_W1l[HID_ * HID_];
__device__ __nv_bfloat16 g_W2h[HID_ * HID_];
__device__ __nv_bfloat16 g_W2l[HID_ * HID_];
__device__ float g_P[(size_t)HW_ * NA_ * HW_];    // logits, layout [w][a][s] fp32
__device__ __half g_Pt[(size_t)HW_ * NA_ * HW_];  // [w][a][s] fp16
__device__ float g_R[ROWS_ * HW_];
__device__ float g_V[ROWS_ * HW_];                // fp32 values
__device__ __half g_Wq[ROWS_ * HW_];              // fp16 centered values
__device__ float g_mu[ROWS_];                     // per-row mean

// ------------------------- ptx helpers -------------------------------------
__device__ __forceinline__ void fma2(ull& d, ull a, ull b) {
    asm("fma.rn.f32x2 %0, %1, %2, %0;" : "+l"(d) : "l"(a), "l"(b));
}
__device__ __forceinline__ float2 unpack2(ull u) {
    float2 f;
    asm("mov.b64 {%0, %1}, %2;" : "=f"(f.x), "=f"(f.y) : "l"(u));
    return f;
}
__device__ __forceinline__ ull pack2(float x, float y) {
    ull u;
    asm("mov.b64 %0, {%1, %2};" : "=l"(u) : "f"(x), "f"(y));
    return u;
}
__device__ __forceinline__ uint32_t smem_u32(const void* p) {
    uint32_t a;
    asm("{ .reg .u64 t; cvta.to.shared.u64 t, %1; cvt.u32.u64 %0, t; }" : "=r"(a) : "l"(p));
    return a;
}
__device__ __forceinline__ void cp_async16(uint32_t dst, const void* src) {
    asm volatile("cp.async.cg.shared.global [%0], [%1], 16;" ::"r"(dst), "l"(src) : "memory");
}
#define CP_COMMIT() asm volatile("cp.async.commit_group;" ::: "memory")

__device__ __forceinline__ void ldsm_x4(uint32_t* r, uint32_t addr) {
    asm volatile("ldmatrix.sync.aligned.m8n8.x4.shared.b16 {%0,%1,%2,%3}, [%4];"
                 : "=r"(r[0]), "=r"(r[1]), "=r"(r[2]), "=r"(r[3]) : "r"(addr));
}
__device__ __forceinline__ void mma16816(float* c, const uint32_t* a, const uint32_t* b) {
    asm volatile(
        "mma.sync.aligned.m16n8k16.row.col.f32.bf16.bf16.f32 "
        "{%0,%1,%2,%3}, {%4,%5,%6,%7}, {%8,%9}, {%0,%1,%2,%3};"
        : "+f"(c[0]), "+f"(c[1]), "+f"(c[2]), "+f"(c[3])
        : "r"(a[0]), "r"(a[1]), "r"(a[2]), "r"(a[3]), "r"(b[0]), "r"(b[1]));
}
__device__ __forceinline__ void mma16816h(float* c, const uint32_t* a, const uint32_t* b) {
    asm volatile(
        "mma.sync.aligned.m16n8k16.row.col.f32.f16.f16.f32 "
        "{%0,%1,%2,%3}, {%4,%5,%6,%7}, {%8,%9}, {%0,%1,%2,%3};"
        : "+f"(c[0]), "+f"(c[1]), "+f"(c[2]), "+f"(c[3])
        : "r"(a[0]), "r"(a[1]), "r"(a[2]), "r"(a[3]), "r"(b[0]), "r"(b[1]));
}

// swizzled 16KB tile: 128 rows x 128B, seg16 c in 0..7: addr = r*128 + ((c ^ (r&7))<<4)
#define TILE16 16384
__device__ __forceinline__ uint32_t sw_addr(uint32_t base, int r, int c16) {
    return base + r * 128 + (((uint32_t)(c16 ^ (r & 7))) << 4);
}
// bf16 tile loader: 128 rows x 64 elems, stride in elements
__device__ __forceinline__ void load_tile_sw(uint32_t dst, const __nv_bfloat16* src, int stride,
                                             int tid) {
#pragma unroll
    for (int i = 0; i < 4; ++i) {
        int lin = tid + i * 256;
        int r = lin >> 3, seg = lin & 7;
        cp_async16(sw_addr(dst, r, seg), src + (size_t)r * stride + seg * 8);
    }
}
// generic byte-based tile loader: 128 rows x 128B per row from rowBytes-strided src
__device__ __forceinline__ void load_tile_g(uint32_t dst, const void* src, int rowBytes, int tid) {
    const char* s = (const char*)src;
#pragma unroll
    for (int i = 0; i < 4; ++i) {
        int lin = tid + i * 256;
        int r = lin >> 3, seg = lin & 7;
        cp_async16(sw_addr(dst, r, seg), s + (size_t)r * rowBytes + seg * 16);
    }
}

// ------------------------- K1: gi ------------------------------------------
__global__ void gi_kernel(const float* __restrict__ S, const float* __restrict__ w_ih,
                          const float* __restrict__ b_ih) {
    __shared__ float Ss[HID_];
    int blk = blockIdx.x;
    int o = threadIdx.x;
    if (o < HID_) Ss[o] = S[blk * HID_ + o];
    __syncthreads();
    float acc = b_ih[o];
#pragma unroll 8
    for (int k = 0; k < HID_; k += 4) {
        float4 w = *reinterpret_cast<const float4*>(&w_ih[o * HID_ + k]);
        acc += Ss[k] * w.x + Ss[k + 1] * w.y + Ss[k + 2] * w.z + Ss[k + 3] * w.w;
    }
    g_gi[blk * 384 + o] = acc;
}

// ------------------------- K2: GRU (register weights, ILP4) ----------------
__global__ __launch_bounds__(384, 1) void gru_kernel(const float* __restrict__ w_hh,
                                                     const float* __restrict__ b_hh) {
    __shared__ __align__(16) float hs[HID_];
    __shared__ float ghs[384];
    int o = threadIdx.x;

    ull w2[64];
#pragma unroll
    for (int i = 0; i < 64; ++i) {
        float2 v = reinterpret_cast<const float2*>(w_hh)[o * 64 + i];
        w2[i] = pack2(v.x, v.y);
    }
    if (o < HID_) hs[o] = 0.0f;
    float bh = b_hh[o];
    __syncthreads();

    for (int t = 0; t < HW_; ++t) {
        ull z = pack2(0.0f, 0.0f);
        ull a0 = pack2(bh, 0.0f), a1 = z, a2 = z, a3 = z;
        const ull* h2 = reinterpret_cast<const ull*>(hs);
#pragma unroll
        for (int i = 0; i < 64; i += 4) {
            fma2(a0, h2[i], w2[i]);
            fma2(a1, h2[i + 1], w2[i + 1]);
            fma2(a2, h2[i + 2], w2[i + 2]);
            fma2(a3, h2[i + 3], w2[i + 3]);
        }
        float2 p0 = unpack2(a0), p1 = unpack2(a1), p2 = unpack2(a2), p3 = unpack2(a3);
        ghs[o] = (p0.x + p0.y) + (p1.x + p1.y) + ((p2.x + p2.y) + (p3.x + p3.y));
        __syncthreads();
        if (o < HID_) {
            float gir = g_gi[t * 384 + o];
            float giz = g_gi[t * 384 + 128 + o];
            float gin = g_gi[t * 384 + 256 + o];
            float r = 1.0f / (1.0f + expf(-(gir + ghs[o])));
            float zz = 1.0f / (1.0f + expf(-(giz + ghs[o + 128])));
            float n = tanhf(gin + r * ghs[o + 256]);
            float hn = (1.0f - zz) * n + zz * hs[o];
            hs[o] = hn;
            __nv_bfloat16 hi = __float2bfloat16(hn);
            g_Kh[t * HID_ + o] = hi;
            g_Kl[t * HID_ + o] = __float2bfloat16(hn - __bfloat162float(hi));
        }
        __syncthreads();
    }
}

// ------------------------- K3a: split W1, W2 -------------------------------
__global__ void wsplit_kernel(const float* __restrict__ W1, const float* __restrict__ W2) {
    const float* src = blockIdx.x ? W2 : W1;
    __nv_bfloat16* dh = blockIdx.x ? g_W2h : g_W1h;
    __nv_bfloat16* dl = blockIdx.x ? g_W2l : g_W1l;
    for (int i = threadIdx.x; i < HID_ * HID_; i += blockDim.x) {
        float v = src[i];
        __nv_bfloat16 hi = __float2bfloat16(v);
        dh[i] = hi;
        dl[i] = __float2bfloat16(v - __bfloat162float(hi));
    }
}

// ------------------------- K3b: X = A + S, bf16 split ----------------------
__global__ __launch_bounds__(256) void xprep_kernel(const float* __restrict__ A,
                                                    const float* __restrict__ S) {
    int w = blockIdx.x, ab = blockIdx.y;
    int al = threadIdx.x >> 4, k8 = (threadIdx.x & 15) * 8;
    int a = ab * 16 + al;
    float4 a0 = *reinterpret_cast<const float4*>(&A[a * HID_ + k8]);
    float4 a1 = *reinterpret_cast<const float4*>(&A[a * HID_ + k8 + 4]);
    float4 s0 = *reinterpret_cast<const float4*>(&S[w * HID_ + k8]);
    float4 s1 = *reinterpret_cast<const float4*>(&S[w * HID_ + k8 + 4]);
    float v[8] = {a0.x + s0.x, a0.y + s0.y, a0.z + s0.z, a0.w + s0.w,
                  a1.x + s1.x, a1.y + s1.y, a1.z + s1.z, a1.w + s1.w};
    __nv_bfloat16 h8[8], l8[8];
#pragma unroll
    for (int i = 0; i < 8; ++i) {
        h8[i] = __float2bfloat16(v[i]);
        l8[i] = __float2bfloat16(v[i] - __bfloat162float(h8[i]));
    }
    size_t off = ((size_t)w * NA_ + a) * HID_ + k8;
    *reinterpret_cast<uint4*>(&g_Xh[off]) = *reinterpret_cast<uint4*>(h8);
    *reinterpret_cast<uint4*>(&g_Xl[off]) = *reinterpret_cast<uint4*>(l8);
}

// ------------------------- K4: unified MLP layer via mma (bf16 3-prod) -----
__global__ __launch_bounds__(256, 1) void mlp_mma(int layer, const float* __restrict__ bias) {
    extern __shared__ char smem[];
    uint32_t sb = smem_u32(smem);
    int tid = threadIdx.x, wid = tid >> 5, lane = tid & 31;
    int rt = blockIdx.x;
    int wr = wid >> 1, wc = wid & 1;

    const __nv_bfloat16* xh = layer ? g_Y1h : g_Xh;
    const __nv_bfloat16* xl = layer ? g_Y1l : g_Xl;
    const __nv_bfloat16* wh = layer ? g_W2h : g_W1h;
    const __nv_bfloat16* wl = layer ? g_W2l : g_W1l;
    __nv_bfloat16* dh = layer ? g_Y2h : g_Y1h;
    __nv_bfloat16* dl = layer ? g_Y2l : g_Y1l;

#pragma unroll
    for (int c = 0; c < 2; ++c) {
        load_tile_sw(sb + (0 * 2 + c) * TILE16, xh + (size_t)rt * 16384 + c * 64, 128, tid);
        load_tile_sw(sb + (1 * 2 + c) * TILE16, xl + (size_t)rt * 16384 + c * 64, 128, tid);
        load_tile_sw(sb + (2 * 2 + c) * TILE16, wh + c * 64, 128, tid);
        load_tile_sw(sb + (3 * 2 + c) * TILE16, wl + c * 64, 128, tid);
    }
    CP_COMMIT();
    asm volatile("cp.async.wait_group 0;" ::: "memory");
    __syncthreads();

    float acc[2][8][4];
#pragma unroll
    for (int mb = 0; mb < 2; ++mb)
#pragma unroll
        for (int nt = 0; nt < 8; ++nt)
#pragma unroll
            for (int q = 0; q < 4; ++q) acc[mb][nt][q] = 0.0f;

#pragma unroll
    for (int c = 0; c < 2; ++c) {
        uint32_t ahT = sb + c * TILE16, alT = sb + (2 + c) * TILE16;
        uint32_t bhT = sb + (4 + c) * TILE16, blT = sb + (6 + c) * TILE16;
#pragma unroll
        for (int kk = 0; kk < 4; ++kk) {
            uint32_t ah[2][4], al[2][4];
#pragma unroll
            for (int mb = 0; mb < 2; ++mb) {
                int r = wr * 32 + mb * 16 + (lane & 15);
                int c16 = (lane >> 4) + kk * 2;
                ldsm_x4(ah[mb], sw_addr(ahT, r, c16));
                ldsm_x4(al[mb], sw_addr(alT, r, c16));
            }
            uint32_t bh[8][2], bl[8][2];
#pragma unroll
            for (int np = 0; np < 4; ++np) {
                int n = wc * 64 + np * 16 + ((lane >> 4) << 3) + (lane & 7);
                int c16 = ((lane >> 3) & 1) + kk * 2;
                uint32_t r4[4];
                ldsm_x4(r4, sw_addr(bhT, n, c16));
                bh[np * 2][0] = r4[0]; bh[np * 2][1] = r4[1];
                bh[np * 2 + 1][0] = r4[2]; bh[np * 2 + 1][1] = r4[3];
                ldsm_x4(r4, sw_addr(blT, n, c16));
                bl[np * 2][0] = r4[0]; bl[np * 2][1] = r4[1];
                bl[np * 2 + 1][0] = r4[2]; bl[np * 2 + 1][1] = r4[3];
            }
#pragma unroll
            for (int mb = 0; mb < 2; ++mb)
#pragma unroll
                for (int nt = 0; nt < 8; ++nt) {
                    mma16816(acc[mb][nt], ah[mb], bh[nt]);
                    mma16816(acc[mb][nt], ah[mb], bl[nt]);
                    mma16816(acc[mb][nt], al[mb], bh[nt]);
                }
        }
    }
    int g = lane >> 2;
#pragma unroll
    for (int mb = 0; mb < 2; ++mb)
#pragma unroll
        for (int nt = 0; nt < 8; ++nt) {
            int col = wc * 64 + nt * 8 + (lane & 3) * 2;
            float bb0 = bias[col], bb1 = bias[col + 1];
#pragma unroll
            for (int h = 0; h < 2; ++h) {
                int row = rt * 128 + wr * 32 + mb * 16 + g + h * 8;
                float o0 = fmaxf(acc[mb][nt][2 * h] + bb0, 0.0f);
                float o1 = fmaxf(acc[mb][nt][2 * h + 1] + bb1, 0.0f);
                __nv_bfloat16 h0 = __float2bfloat16(o0);
                __nv_bfloat16 h1 = __float2bfloat16(o1);
                __nv_bfloat162 hp, lp;
                hp.x = h0; hp.y = h1;
                lp.x = __float2bfloat16(o0 - __bfloat162float(h0));
                lp.y = __float2bfloat16(o1 - __bfloat162float(h1));
                *reinterpret_cast<__nv_bfloat162*>(&dh[(size_t)row * HID_ + col]) = hp;
                *reinterpret_cast<__nv_bfloat162*>(&dl[(size_t)row * HID_ + col]) = lp;
            }
        }
}

// ------------------------- K5: logits via mma.sync, writes [w][a][s] -------
__global__ __launch_bounds__(256, 1) void logits_mma() {
    extern __shared__ char smem[];
    uint32_t sb = smem_u32(smem);
    int tid = threadIdx.x, wid = tid >> 5, lane = tid & 31;
    int s0 = blockIdx.x * 128;
    int w = blockIdx.y;
    int wr = wid >> 1, wc = wid & 1;

#pragma unroll
    for (int c = 0; c < 2; ++c) {
        load_tile_sw(sb + (0 * 2 + c) * TILE16, g_Kh + (size_t)s0 * 128 + c * 64, 128, tid);
        load_tile_sw(sb + (1 * 2 + c) * TILE16, g_Kl + (size_t)s0 * 128 + c * 64, 128, tid);
        load_tile_sw(sb + (2 * 2 + c) * TILE16, g_Y2h + (size_t)w * 128 * 128 + c * 64, 128, tid);
        load_tile_sw(sb + (3 * 2 + c) * TILE16, g_Y2l + (size_t)w * 128 * 128 + c * 64, 128, tid);
    }
    CP_COMMIT();
    asm volatile("cp.async.wait_group 0;" ::: "memory");
    __syncthreads();

    float acc[2][8][4];
#pragma unroll
    for (int mb = 0; mb < 2; ++mb)
#pragma unroll
        for (int nt = 0; nt < 8; ++nt)
#pragma unroll
            for (int q = 0; q < 4; ++q) acc[mb][nt][q] = 0.0f;

#pragma unroll
    for (int c = 0; c < 2; ++c) {
        uint32_t ahT = sb + c * TILE16, alT = sb + (2 + c) * TILE16;
        uint32_t bhT = sb + (4 + c) * TILE16, blT = sb + (6 + c) * TILE16;
#pragma unroll
        for (int kk = 0; kk < 4; ++kk) {
            uint32_t ah[2][4], al[2][4];
#pragma unroll
            for (int mb = 0; mb < 2; ++mb) {
                int r = wr * 32 + mb * 16 + (lane & 15);
                int c16 = (lane >> 4) + kk * 2;
                ldsm_x4(ah[mb], sw_addr(ahT, r, c16));
                ldsm_x4(al[mb], sw_addr(alT, r, c16));
            }
            uint32_t bh[8][2], bl[8][2];
#pragma unroll
            for (int np = 0; np < 4; ++np) {
                int n = wc * 64 + np * 16 + ((lane >> 4) << 3) + (lane & 7);
                int c16 = ((lane >> 3) & 1) + kk * 2;
                uint32_t r4[4];
                ldsm_x4(r4, sw_addr(bhT, n, c16));
                bh[np * 2][0] = r4[0]; bh[np * 2][1] = r4[1];
                bh[np * 2 + 1][0] = r4[2]; bh[np * 2 + 1][1] = r4[3];
                ldsm_x4(r4, sw_addr(blT, n, c16));
                bl[np * 2][0] = r4[0]; bl[np * 2][1] = r4[1];
                bl[np * 2 + 1][0] = r4[2]; bl[np * 2 + 1][1] = r4[3];
            }
#pragma unroll
            for (int mb = 0; mb < 2; ++mb)
#pragma unroll
                for (int nt = 0; nt < 8; ++nt) {
                    mma16816(acc[mb][nt], ah[mb], bh[nt]);
                    mma16816(acc[mb][nt], ah[mb], bl[nt]);
                    mma16816(acc[mb][nt], al[mb], bh[nt]);
                }
        }
    }
    // transposed store: L[w][a=col][s=s0+row]
    int g = lane >> 2;
#pragma unroll
    for (int mb = 0; mb < 2; ++mb)
#pragma unroll
        for (int nt = 0; nt < 8; ++nt) {
            int row = wr * 32 + mb * 16 + g;
            int col = wc * 64 + nt * 8 + (lane & 3) * 2;
            size_t b0 = ((size_t)w * NA_ + col) * HW_ + s0 + row;
            g_P[b0] = acc[mb][nt][0];
            g_P[b0 + HW_] = acc[mb][nt][1];
            g_P[b0 + 8] = acc[mb][nt][2];
            g_P[b0 + HW_ + 8] = acc[mb][nt][3];
        }
}

// ------------------------- K6: row softmax over s + fp16 out ---------------
__global__ __launch_bounds__(256) void softmax_rows() {
    int wid = threadIdx.x >> 5, lane = threadIdx.x & 31;
    size_t row = (size_t)blockIdx.x * 8 + wid;  // 0..32767
    const float* base = g_P + row * HW_;
    float4 a = *reinterpret_cast<const float4*>(base + lane * 8);
    float4 b = *reinterpret_cast<const float4*>(base + lane * 8 + 4);
    float m = fmaxf(fmaxf(fmaxf(a.x, a.y), fmaxf(a.z, a.w)),
                    fmaxf(fmaxf(b.x, b.y), fmaxf(b.z, b.w)));
#pragma unroll
    for (int o = 16; o; o >>= 1) m = fmaxf(m, __shfl_xor_sync(0xffffffffu, m, o));
    float e[8];
    e[0] = expf(a.x - m); e[1] = expf(a.y - m); e[2] = expf(a.z - m); e[3] = expf(a.w - m);
    e[4] = expf(b.x - m); e[5] = expf(b.y - m); e[6] = expf(b.z - m); e[7] = expf(b.w - m);
    float s = ((e[0] + e[1]) + (e[2] + e[3])) + ((e[4] + e[5]) + (e[6] + e[7]));
#pragma unroll
    for (int o = 16; o; o >>= 1) s += __shfl_xor_sync(0xffffffffu, s, o);
    float inv = 1.0f / s;
    __half h8[8];
#pragma unroll
    for (int i = 0; i < 8; ++i) h8[i] = __float2half(e[i] * inv);
    *reinterpret_cast<uint4*>(g_Pt + row * HW_ + lane * 8) = *reinterpret_cast<uint4*>(h8);
}

// ------------------------- K7: rewards + V0 init + center/split ------------
__global__ __launch_bounds__(256) void init_kernel(const float* __restrict__ inputs) {
    __shared__ float part[8];
    int row = blockIdx.x, t = threadIdx.x;
    int wid = t >> 5, lane = t & 31;
    float v = inputs[row * 257 + t];
    g_R[row * HW_ + t] = v;
    g_V[row * HW_ + t] = v;
    float s = v;
#pragma unroll
    for (int o = 16; o; o >>= 1) s += __shfl_xor_sync(0xffffffffu, s, o);
    if (lane == 0) part[wid] = s;
    __syncthreads();
    float tot = ((part[0] + part[1]) + (part[2] + part[3])) +
                ((part[4] + part[5]) + (part[6] + part[7]));
    float mu = tot * (1.0f / 256.0f);
    g_Wq[row * HW_ + t] = __float2half(v - mu);
    if (t == 0) g_mu[row] = mu;
}

// ------------------------- K7b: center + fp16 split of V -------------------
__global__ __launch_bounds__(256) void vsplit_kernel() {
    int wid = threadIdx.x >> 5, lane = threadIdx.x & 31;
    int row = blockIdx.x * 8 + wid;
    const float* v = g_V + row * HW_;
    float4 a = *reinterpret_cast<const float4*>(v + lane * 8);
    float4 b = *reinterpret_cast<const float4*>(v + lane * 8 + 4);
    float s = ((a.x + a.y) + (a.z + a.w)) + ((b.x + b.y) + (b.z + b.w));
#pragma unroll
    for (int o = 16; o; o >>= 1) s += __shfl_xor_sync(0xffffffffu, s, o);
    float mu = s * (1.0f / 256.0f);
    __half h8[8];
    h8[0] = __float2half(a.x - mu);
    h8[1] = __float2half(a.y - mu);
    h8[2] = __float2half(a.z - mu);
    h8[3] = __float2half(a.w - mu);
    h8[4] = __float2half(b.x - mu);
    h8[5] = __float2half(b.y - mu);
    h8[6] = __float2half(b.z - mu);
    h8[7] = __float2half(b.w - mu);
    *reinterpret_cast<uint4*>(g_Wq + row * HW_ + lane * 8) = *reinterpret_cast<uint4*>(h8);
    if (lane == 0) g_mu[row] = mu;
}

// ------------------------- K8: Bellman via fp16 mma (1 product, centered) --
#define POFF_   65536
#define BSMEM_  98304

__global__ __launch_bounds__(256, 1) void bellman_h() {
    extern __shared__ char smem[];
    __shared__ float red_s[8][32];
    uint32_t sb = smem_u32(smem);
    int tid = threadIdx.x, wid = tid >> 5, lane = tid & 31;
    int rb = blockIdx.x * 128;
    int w = blockIdx.y;
    int wr = wid >> 1, wc = wid & 1;

    const char* wsrc = (const char*)(g_Wq + (size_t)rb * 256);
    const char* pbase = (const char*)g_Pt + (size_t)w * 65536;

#pragma unroll
    for (int c = 0; c < 4; ++c) load_tile_g(sb + c * TILE16, wsrc + c * 128, 512, tid);
    load_tile_g(sb + POFF_, pbase, 512, tid);
    CP_COMMIT();
    load_tile_g(sb + POFF_ + TILE16, pbase + 128, 512, tid);
    CP_COMMIT();

    float acc[2][8][4];
#pragma unroll
    for (int mb = 0; mb < 2; ++mb)
#pragma unroll
        for (int nt = 0; nt < 8; ++nt)
#pragma unroll
            for (int q = 0; q < 4; ++q) acc[mb][nt][q] = 0.0f;

#pragma unroll
    for (int i = 0; i < 4; ++i) {
        if (i < 3)
            asm volatile("cp.async.wait_group 1;" ::: "memory");
        else
            asm volatile("cp.async.wait_group 0;" ::: "memory");
        __syncthreads();

        uint32_t vT = sb + i * TILE16;
        uint32_t pT = sb + POFF_ + (i & 1) * TILE16;

#pragma unroll
        for (int kk = 0; kk < 4; ++kk) {
            uint32_t ah[2][4];
#pragma unroll
            for (int mb = 0; mb < 2; ++mb) {
                int r = wr * 32 + mb * 16 + (lane & 15);
                int c16 = (lane >> 4) + kk * 2;
                ldsm_x4(ah[mb], sw_addr(vT, r, c16));
            }
            uint32_t bh[8][2];
#pragma unroll
            for (int np = 0; np < 4; ++np) {
                int n = wc * 64 + np * 16 + ((lane >> 4) << 3) + (lane & 7);
                int c16 = ((lane >> 3) & 1) + kk * 2;
                uint32_t r4[4];
                ldsm_x4(r4, sw_addr(pT, n, c16));
                bh[np * 2][0] = r4[0]; bh[np * 2][1] = r4[1];
                bh[np * 2 + 1][0] = r4[2]; bh[np * 2 + 1][1] = r4[3];
            }
#pragma unroll
            for (int mb = 0; mb < 2; ++mb)
#pragma unroll
                for (int nt = 0; nt < 8; ++nt) mma16816h(acc[mb][nt], ah[mb], bh[nt]);
        }
        __syncthreads();

        if (i < 2) {
            load_tile_g(sb + POFF_ + (i & 1) * TILE16, pbase + (i + 2) * 128, 512, tid);
            CP_COMMIT();
        }
    }

    int g = lane >> 2;
#pragma unroll
    for (int mb = 0; mb < 2; ++mb) {
        float mA = -1e30f, mB = -1e30f;
#pragma unroll
        for (int nt = 0; nt < 8; ++nt) {
            mA = fmaxf(mA, fmaxf(acc[mb][nt][0], acc[mb][nt][1]));
            mB = fmaxf(mB, fmaxf(acc[mb][nt][2], acc[mb][nt][3]));
        }
        mA = fmaxf(mA, __shfl_xor_sync(0xffffffffu, mA, 1));
        mA = fmaxf(mA, __shfl_xor_sync(0xffffffffu, mA, 2));
        mB = fmaxf(mB, __shfl_xor_sync(0xffffffffu, mB, 1));
        mB = fmaxf(mB, __shfl_xor_sync(0xffffffffu, mB, 2));
        if ((lane & 3) == 0) {
            red_s[wid][mb * 16 + g] = mA;
            red_s[wid][mb * 16 + 8 + g] = mB;
        }
    }
    __syncthreads();
    if (tid < 128) {
        int wrr = tid >> 5, rl = tid & 31;
        float m = fmaxf(red_s[wrr * 2][rl], red_s[wrr * 2 + 1][rl]);
        int row = rb + tid;
        g_V[row * HW_ + w] = g_R[row * HW_ + w] + m + g_mu[row];
    }
}

// ------------------------- K9: output assembly -----------------------------
__global__ void assemble_kernel(const float* __restrict__ rnn_hxs, float* __restrict__ out,
                                int out_size) {
    int idx = blockIdx.x * blockDim.x + threadIdx.x;
    if (idx >= out_size || idx >= OUTT_) return;
    int row, c;
    if (idx < OUT1_) {
        row = idx / HX_;
        c = idx - row * HX_;
    } else {
        int k = idx - OUT1_;
        int r2 = k / HX_;
        c = k - r2 * HX_;
        row = 448 + r2;
    }
    float v = (c < PASS_) ? rnn_hxs[row * HX_ + c] : g_V[row * HW_ + (c - PASS_)];
    out[idx] = v;
}

// ------------------------- launcher ----------------------------------------
extern "C" void kernel_launch(void* const* d_in, const int* in_sizes, int n_in,
                              void* d_out, int out_size) {
    const float* inputs = (const float*)d_in[0];
    const float* rnn_hxs = (const float*)d_in[1];
    const float* S = (const float*)d_in[2];
    const float* A = (const float*)d_in[3];
    const float* w_ih = (const float*)d_in[4];
    const float* w_hh = (const float*)d_in[5];
    const float* b_ih = (const float*)d_in[6];
    const float* b_hh = (const float*)d_in[7];
    const float* W1 = (const float*)d_in[8];
    const float* b1 = (const float*)d_in[9];
    const float* W2 = (const float*)d_in[10];
    const float* b2 = (const float*)d_in[11];
    float* out = (float*)d_out;

    cudaFuncSetAttribute(bellman_h, cudaFuncAttributeMaxDynamicSharedMemorySize, BSMEM_);
    cudaFuncSetAttribute(logits_mma, cudaFuncAttributeMaxDynamicSharedMemorySize, 131072);
    cudaFuncSetAttribute(mlp_mma, cudaFuncAttributeMaxDynamicSharedMemorySize, 131072);

    // fork a side stream (created per call; intentionally not destroyed — a
    // stream referenced by an in-progress capture must outlive the capture).
    cudaStream_t s2;
    cudaEvent_t evFork, evJoin;
    cudaStreamCreateWithFlags(&s2, cudaStreamNonBlocking);
    cudaEventCreateWithFlags(&evFork, cudaEventDisableTiming);
    cudaEventCreateWithFlags(&evJoin, cudaEventDisableTiming);

    cudaEventRecord(evFork, 0);
    cudaStreamWaitEvent(s2, evFork, 0);

    // branch A (legacy stream): GRU chain (single-SM, long)
    gi_kernel<<<HW_, 384>>>(S, w_ih, b_ih);
    gru_kernel<<<1, 384>>>(w_hh, b_hh);

    // branch B (side stream): MLP chain + init (independent of GRU)
    wsplit_kernel<<<2, 256, 0, s2>>>(W1, W2);
    xprep_kernel<<<dim3(HW_, 8), 256, 0, s2>>>(A, S);
    mlp_mma<<<256, 256, 131072, s2>>>(0, b1);
    mlp_mma<<<256, 256, 131072, s2>>>(1, b2);
    init_kernel<<<ROWS_, 256, 0, s2>>>(inputs);

    cudaEventRecord(evJoin, s2);
    cudaStreamWaitEvent(0, evJoin, 0);

    // joined: logits needs K (branch A) and Y2 (branch B)
    logits_mma<<<dim3(2, HW_), 256, 131072>>>();
    softmax_rows<<<HW_ * NA_ / 8, 256>>>();
    for (int it = 0; it < 15; ++it) {
        bellman_h<<<dim3(4, HW_), 256, BSMEM_>>>();
        if (it < 14) vsplit_kernel<<<ROWS_ / 8, 256>>>();
    }
    int total = out_size < OUTT_ ? out_size : OUTT_;
    assemble_kernel<<<(total + 255) / 256, 256>>>(rnn_hxs, out, out_size);
}

// round 16
// speedup vs baseline: 1.4508x; 1.0004x over previous
#include <cuda_runtime.h>
#include <cuda_bf16.h>
#include <cuda_fp16.h>
#include <math.h>
#include <stdint.h>

// Problem constants
#define T_      8
#define N_      64
#define HW_     256
#define HID_    128
#define NA_     128
#define HX_     514
#define PASS_   258
#define ROWS_   512
#define OUT1_   263168
#define OUTT_   296064

#define MUSC_   (1.0f / (4096.0f * 256.0f))

typedef unsigned long long ull;

// ------------------------- scratch (device globals; no allocs) -------------
__device__ float g_gi[HW_ * 384];
__device__ __nv_bfloat16 g_Kh[HW_ * HID_];
__device__ __nv_bfloat16 g_Kl[HW_ * HID_];
__device__ __nv_bfloat16 g_Xh[HW_ * NA_ * HID_];   // X = A+S, bf16 hi/lo
__device__ __nv_bfloat16 g_Xl[HW_ * NA_ * HID_];
__device__ __nv_bfloat16 g_Y1h[HW_ * NA_ * HID_];
__device__ __nv_bfloat16 g_Y1l[HW_ * NA_ * HID_];
__device__ __nv_bfloat16 g_Y2h[HW_ * NA_ * HID_];
__device__ __nv_bfloat16 g_Y2l[HW_ * NA_ * HID_];
__device__ __nv_bfloat16 g_W1h[HID_ * HID_];
__device__ __nv_bfloat16 g_W1l[HID_ * HID_];
__device__ __nv_bfloat16 g_W2h[HID_ * HID_];
__device__ __nv_bfloat16 g_W2l[HID_ * HID_];
__device__ float g_P[(size_t)HW_ * NA_ * HW_];    // logits, layout [w][a][s] fp32
__device__ __half g_Pt[(size_t)HW_ * NA_ * HW_];  // [w][a][s] fp16
__device__ float g_R[ROWS_ * HW_];
__device__ float g_V[ROWS_ * HW_];                // fp32 values
__device__ __half g_Wq[2][ROWS_ * HW_];           // fp16 centered values (ping-pong)
__device__ int g_slot[16][ROWS_];                 // int row-sums of V per iteration

// ------------------------- ptx helpers -------------------------------------
__device__ __forceinline__ void fma2(ull& d, ull a, ull b) {
    asm("fma.rn.f32x2 %0, %1, %2, %0;" : "+l"(d) : "l"(a), "l"(b));
}
__device__ __forceinline__ float2 unpack2(ull u) {
    float2 f;
    asm("mov.b64 {%0, %1}, %2;" : "=f"(f.x), "=f"(f.y) : "l"(u));
    return f;
}
__device__ __forceinline__ ull pack2(float x, float y) {
    ull u;
    asm("mov.b64 %0, {%1, %2};" : "=l"(u) : "f"(x), "f"(y));
    return u;
}
__device__ __forceinline__ uint32_t smem_u32(const void* p) {
    uint32_t a;
    asm("{ .reg .u64 t; cvta.to.shared.u64 t, %1; cvt.u32.u64 %0, t; }" : "=r"(a) : "l"(p));
    return a;
}
__device__ __forceinline__ void cp_async16(uint32_t dst, const void* src) {
    asm volatile("cp.async.cg.shared.global [%0], [%1], 16;" ::"r"(dst), "l"(src) : "memory");
}
#define CP_COMMIT() asm volatile("cp.async.commit_group;" ::: "memory")

__device__ __forceinline__ void ldsm_x4(uint32_t* r, uint32_t addr) {
    asm volatile("ldmatrix.sync.aligned.m8n8.x4.shared.b16 {%0,%1,%2,%3}, [%4];"
                 : "=r"(r[0]), "=r"(r[1]), "=r"(r[2]), "=r"(r[3]) : "r"(addr));
}
__device__ __forceinline__ void mma16816(float* c, const uint32_t* a, const uint32_t* b) {
    asm volatile(
        "mma.sync.aligned.m16n8k16.row.col.f32.bf16.bf16.f32 "
        "{%0,%1,%2,%3}, {%4,%5,%6,%7}, {%8,%9}, {%0,%1,%2,%3};"
        : "+f"(c[0]), "+f"(c[1]), "+f"(c[2]), "+f"(c[3])
        : "r"(a[0]), "r"(a[1]), "r"(a[2]), "r"(a[3]), "r"(b[0]), "r"(b[1]));
}
__device__ __forceinline__ void mma16816h(float* c, const uint32_t* a, const uint32_t* b) {
    asm volatile(
        "mma.sync.aligned.m16n8k16.row.col.f32.f16.f16.f32 "
        "{%0,%1,%2,%3}, {%4,%5,%6,%7}, {%8,%9}, {%0,%1,%2,%3};"
        : "+f"(c[0]), "+f"(c[1]), "+f"(c[2]), "+f"(c[3])
        : "r"(a[0]), "r"(a[1]), "r"(a[2]), "r"(a[3]), "r"(b[0]), "r"(b[1]));
}

// swizzled 16KB tile: 128 rows x 128B, seg16 c in 0..7: addr = r*128 + ((c ^ (r&7))<<4)
#define TILE16 16384
__device__ __forceinline__ uint32_t sw_addr(uint32_t base, int r, int c16) {
    return base + r * 128 + (((uint32_t)(c16 ^ (r & 7))) << 4);
}
// bf16 tile loader: 128 rows x 64 elems, stride in elements
__device__ __forceinline__ void load_tile_sw(uint32_t dst, const __nv_bfloat16* src, int stride,
                                             int tid) {
#pragma unroll
    for (int i = 0; i < 4; ++i) {
        int lin = tid + i * 256;
        int r = lin >> 3, seg = lin & 7;
        cp_async16(sw_addr(dst, r, seg), src + (size_t)r * stride + seg * 8);
    }
}
// generic byte-based tile loader: 128 rows x 128B per row from rowBytes-strided src
__device__ __forceinline__ void load_tile_g(uint32_t dst, const void* src, int rowBytes, int tid) {
    const char* s = (const char*)src;
#pragma unroll
    for (int i = 0; i < 4; ++i) {
        int lin = tid + i * 256;
        int r = lin >> 3, seg = lin & 7;
        cp_async16(sw_addr(dst, r, seg), s + (size_t)r * rowBytes + seg * 16);
    }
}

// ------------------------- K1: gi ------------------------------------------
__global__ void gi_kernel(const float* __restrict__ S, const float* __restrict__ w_ih,
                          const float* __restrict__ b_ih) {
    __shared__ float Ss[HID_];
    int blk = blockIdx.x;
    int o = threadIdx.x;
    if (o < HID_) Ss[o] = S[blk * HID_ + o];
    __syncthreads();
    float acc = b_ih[o];
#pragma unroll 8
    for (int k = 0; k < HID_; k += 4) {
        float4 w = *reinterpret_cast<const float4*>(&w_ih[o * HID_ + k]);
        acc += Ss[k] * w.x + Ss[k + 1] * w.y + Ss[k + 2] * w.z + Ss[k + 3] * w.w;
    }
    g_gi[blk * 384 + o] = acc;
}

// ------------------------- K2: GRU (register weights, ILP4) ----------------
__global__ __launch_bounds__(384, 1) void gru_kernel(const float* __restrict__ w_hh,
                                                     const float* __restrict__ b_hh) {
    __shared__ __align__(16) float hs[HID_];
    __shared__ float ghs[384];
    int o = threadIdx.x;

    ull w2[64];
#pragma unroll
    for (int i = 0; i < 64; ++i) {
        float2 v = reinterpret_cast<const float2*>(w_hh)[o * 64 + i];
        w2[i] = pack2(v.x, v.y);
    }
    if (o < HID_) hs[o] = 0.0f;
    float bh = b_hh[o];
    __syncthreads();

    for (int t = 0; t < HW_; ++t) {
        ull z = pack2(0.0f, 0.0f);
        ull a0 = pack2(bh, 0.0f), a1 = z, a2 = z, a3 = z;
        const ull* h2 = reinterpret_cast<const ull*>(hs);
#pragma unroll
        for (int i = 0; i < 64; i += 4) {
            fma2(a0, h2[i], w2[i]);
            fma2(a1, h2[i + 1], w2[i + 1]);
            fma2(a2, h2[i + 2], w2[i + 2]);
            fma2(a3, h2[i + 3], w2[i + 3]);
        }
        float2 p0 = unpack2(a0), p1 = unpack2(a1), p2 = unpack2(a2), p3 = unpack2(a3);
        ghs[o] = (p0.x + p0.y) + (p1.x + p1.y) + ((p2.x + p2.y) + (p3.x + p3.y));
        __syncthreads();
        if (o < HID_) {
            float gir = g_gi[t * 384 + o];
            float giz = g_gi[t * 384 + 128 + o];
            float gin = g_gi[t * 384 + 256 + o];
            float r = 1.0f / (1.0f + expf(-(gir + ghs[o])));
            float zz = 1.0f / (1.0f + expf(-(giz + ghs[o + 128])));
            float n = tanhf(gin + r * ghs[o + 256]);
            float hn = (1.0f - zz) * n + zz * hs[o];
            hs[o] = hn;
            __nv_bfloat16 hi = __float2bfloat16(hn);
            g_Kh[t * HID_ + o] = hi;
            g_Kl[t * HID_ + o] = __float2bfloat16(hn - __bfloat162float(hi));
        }
        __syncthreads();
    }
}

// ------------------------- K3a: split W1, W2 -------------------------------
__global__ void wsplit_kernel(const float* __restrict__ W1, const float* __restrict__ W2) {
    const float* src = blockIdx.x ? W2 : W1;
    __nv_bfloat16* dh = blockIdx.x ? g_W2h : g_W1h;
    __nv_bfloat16* dl = blockIdx.x ? g_W2l : g_W1l;
    for (int i = threadIdx.x; i < HID_ * HID_; i += blockDim.x) {
        float v = src[i];
        __nv_bfloat16 hi = __float2bfloat16(v);
        dh[i] = hi;
        dl[i] = __float2bfloat16(v - __bfloat162float(hi));
    }
}

// ------------------------- K3b: X = A + S, bf16 split ----------------------
__global__ __launch_bounds__(256) void xprep_kernel(const float* __restrict__ A,
                                                    const float* __restrict__ S) {
    int w = blockIdx.x, ab = blockIdx.y;
    int al = threadIdx.x >> 4, k8 = (threadIdx.x & 15) * 8;
    int a = ab * 16 + al;
    float4 a0 = *reinterpret_cast<const float4*>(&A[a * HID_ + k8]);
    float4 a1 = *reinterpret_cast<const float4*>(&A[a * HID_ + k8 + 4]);
    float4 s0 = *reinterpret_cast<const float4*>(&S[w * HID_ + k8]);
    float4 s1 = *reinterpret_cast<const float4*>(&S[w * HID_ + k8 + 4]);
    float v[8] = {a0.x + s0.x, a0.y + s0.y, a0.z + s0.z, a0.w + s0.w,
                  a1.x + s1.x, a1.y + s1.y, a1.z + s1.z, a1.w + s1.w};
    __nv_bfloat16 h8[8], l8[8];
#pragma unroll
    for (int i = 0; i < 8; ++i) {
        h8[i] = __float2bfloat16(v[i]);
        l8[i] = __float2bfloat16(v[i] - __bfloat162float(h8[i]));
    }
    size_t off = ((size_t)w * NA_ + a) * HID_ + k8;
    *reinterpret_cast<uint4*>(&g_Xh[off]) = *reinterpret_cast<uint4*>(h8);
    *reinterpret_cast<uint4*>(&g_Xl[off]) = *reinterpret_cast<uint4*>(l8);
}

// ------------------------- K4: unified MLP layer via mma (bf16 3-prod) -----
__global__ __launch_bounds__(256, 1) void mlp_mma(int layer, const float* __restrict__ bias) {
    extern __shared__ char smem[];
    uint32_t sb = smem_u32(smem);
    int tid = threadIdx.x, wid = tid >> 5, lane = tid & 31;
    int rt = blockIdx.x;
    int wr = wid >> 1, wc = wid & 1;

    const __nv_bfloat16* xh = layer ? g_Y1h : g_Xh;
    const __nv_bfloat16* xl = layer ? g_Y1l : g_Xl;
    const __nv_bfloat16* wh = layer ? g_W2h : g_W1h;
    const __nv_bfloat16* wl = layer ? g_W2l : g_W1l;
    __nv_bfloat16* dh = layer ? g_Y2h : g_Y1h;
    __nv_bfloat16* dl = layer ? g_Y2l : g_Y1l;

#pragma unroll
    for (int c = 0; c < 2; ++c) {
        load_tile_sw(sb + (0 * 2 + c) * TILE16, xh + (size_t)rt * 16384 + c * 64, 128, tid);
        load_tile_sw(sb + (1 * 2 + c) * TILE16, xl + (size_t)rt * 16384 + c * 64, 128, tid);
        load_tile_sw(sb + (2 * 2 + c) * TILE16, wh + c * 64, 128, tid);
        load_tile_sw(sb + (3 * 2 + c) * TILE16, wl + c * 64, 128, tid);
    }
    CP_COMMIT();
    asm volatile("cp.async.wait_group 0;" ::: "memory");
    __syncthreads();

    float acc[2][8][4];
#pragma unroll
    for (int mb = 0; mb < 2; ++mb)
#pragma unroll
        for (int nt = 0; nt < 8; ++nt)
#pragma unroll
            for (int q = 0; q < 4; ++q) acc[mb][nt][q] = 0.0f;

#pragma unroll
    for (int c = 0; c < 2; ++c) {
        uint32_t ahT = sb + c * TILE16, alT = sb + (2 + c) * TILE16;
        uint32_t bhT = sb + (4 + c) * TILE16, blT = sb + (6 + c) * TILE16;
#pragma unroll
        for (int kk = 0; kk < 4; ++kk) {
            uint32_t ah[2][4], al[2][4];
#pragma unroll
            for (int mb = 0; mb < 2; ++mb) {
                int r = wr * 32 + mb * 16 + (lane & 15);
                int c16 = (lane >> 4) + kk * 2;
                ldsm_x4(ah[mb], sw_addr(ahT, r, c16));
                ldsm_x4(al[mb], sw_addr(alT, r, c16));
            }
            uint32_t bh[8][2], bl[8][2];
#pragma unroll
            for (int np = 0; np < 4; ++np) {
                int n = wc * 64 + np * 16 + ((lane >> 4) << 3) + (lane & 7);
                int c16 = ((lane >> 3) & 1) + kk * 2;
                uint32_t r4[4];
                ldsm_x4(r4, sw_addr(bhT, n, c16));
                bh[np * 2][0] = r4[0]; bh[np * 2][1] = r4[1];
                bh[np * 2 + 1][0] = r4[2]; bh[np * 2 + 1][1] = r4[3];
                ldsm_x4(r4, sw_addr(blT, n, c16));
                bl[np * 2][0] = r4[0]; bl[np * 2][1] = r4[1];
                bl[np * 2 + 1][0] = r4[2]; bl[np * 2 + 1][1] = r4[3];
            }
#pragma unroll
            for (int mb = 0; mb < 2; ++mb)
#pragma unroll
                for (int nt = 0; nt < 8; ++nt) {
                    mma16816(acc[mb][nt], ah[mb], bh[nt]);
                    mma16816(acc[mb][nt], ah[mb], bl[nt]);
                    mma16816(acc[mb][nt], al[mb], bh[nt]);
                }
        }
    }
    int g = lane >> 2;
#pragma unroll
    for (int mb = 0; mb < 2; ++mb)
#pragma unroll
        for (int nt = 0; nt < 8; ++nt) {
            int col = wc * 64 + nt * 8 + (lane & 3) * 2;
            float bb0 = bias[col], bb1 = bias[col + 1];
#pragma unroll
            for (int h = 0; h < 2; ++h) {
                int row = rt * 128 + wr * 32 + mb * 16 + g + h * 8;
                float o0 = fmaxf(acc[mb][nt][2 * h] + bb0, 0.0f);
                float o1 = fmaxf(acc[mb][nt][2 * h + 1] + bb1, 0.0f);
                __nv_bfloat16 h0 = __float2bfloat16(o0);
                __nv_bfloat16 h1 = __float2bfloat16(o1);
                __nv_bfloat162 hp, lp;
                hp.x = h0; hp.y = h1;
                lp.x = __float2bfloat16(o0 - __bfloat162float(h0));
                lp.y = __float2bfloat16(o1 - __bfloat162float(h1));
                *reinterpret_cast<__nv_bfloat162*>(&dh[(size_t)row * HID_ + col]) = hp;
                *reinterpret_cast<__nv_bfloat162*>(&dl[(size_t)row * HID_ + col]) = lp;
            }
        }
}

// ------------------------- K5: logits via mma.sync, writes [w][a][s] -------
__global__ __launch_bounds__(256, 1) void logits_mma() {
    extern __shared__ char smem[];
    uint32_t sb = smem_u32(smem);
    int tid = threadIdx.x, wid = tid >> 5, lane = tid & 31;
    int s0 = blockIdx.x * 128;
    int w = blockIdx.y;
    int wr = wid >> 1, wc = wid & 1;

#pragma unroll
    for (int c = 0; c < 2; ++c) {
        load_tile_sw(sb + (0 * 2 + c) * TILE16, g_Kh + (size_t)s0 * 128 + c * 64, 128, tid);
        load_tile_sw(sb + (1 * 2 + c) * TILE16, g_Kl + (size_t)s0 * 128 + c * 64, 128, tid);
        load_tile_sw(sb + (2 * 2 + c) * TILE16, g_Y2h + (size_t)w * 128 * 128 + c * 64, 128, tid);
        load_tile_sw(sb + (3 * 2 + c) * TILE16, g_Y2l + (size_t)w * 128 * 128 + c * 64, 128, tid);
    }
    CP_COMMIT();
    asm volatile("cp.async.wait_group 0;" ::: "memory");
    __syncthreads();

    float acc[2][8][4];
#pragma unroll
    for (int mb = 0; mb < 2; ++mb)
#pragma unroll
        for (int nt = 0; nt < 8; ++nt)
#pragma unroll
            for (int q = 0; q < 4; ++q) acc[mb][nt][q] = 0.0f;

#pragma unroll
    for (int c = 0; c < 2; ++c) {
        uint32_t ahT = sb + c * TILE16, alT = sb + (2 + c) * TILE16;
        uint32_t bhT = sb + (4 + c) * TILE16, blT = sb + (6 + c) * TILE16;
#pragma unroll
        for (int kk = 0; kk < 4; ++kk) {
            uint32_t ah[2][4], al[2][4];
#pragma unroll
            for (int mb = 0; mb < 2; ++mb) {
                int r = wr * 32 + mb * 16 + (lane & 15);
                int c16 = (lane >> 4) + kk * 2;
                ldsm_x4(ah[mb], sw_addr(ahT, r, c16));
                ldsm_x4(al[mb], sw_addr(alT, r, c16));
            }
            uint32_t bh[8][2], bl[8][2];
#pragma unroll
            for (int np = 0; np < 4; ++np) {
                int n = wc * 64 + np * 16 + ((lane >> 4) << 3) + (lane & 7);
                int c16 = ((lane >> 3) & 1) + kk * 2;
                uint32_t r4[4];
                ldsm_x4(r4, sw_addr(bhT, n, c16));
                bh[np * 2][0] = r4[0]; bh[np * 2][1] = r4[1];
                bh[np * 2 + 1][0] = r4[2]; bh[np * 2 + 1][1] = r4[3];
                ldsm_x4(r4, sw_addr(blT, n, c16));
                bl[np * 2][0] = r4[0]; bl[np * 2][1] = r4[1];
                bl[np * 2 + 1][0] = r4[2]; bl[np * 2 + 1][1] = r4[3];
            }
#pragma unroll
            for (int mb = 0; mb < 2; ++mb)
#pragma unroll
                for (int nt = 0; nt < 8; ++nt) {
                    mma16816(acc[mb][nt], ah[mb], bh[nt]);
                    mma16816(acc[mb][nt], ah[mb], bl[nt]);
                    mma16816(acc[mb][nt], al[mb], bh[nt]);
                }
        }
    }
    // transposed store: L[w][a=col][s=s0+row]
    int g = lane >> 2;
#pragma unroll
    for (int mb = 0; mb < 2; ++mb)
#pragma unroll
        for (int nt = 0; nt < 8; ++nt) {
            int row = wr * 32 + mb * 16 + g;
            int col = wc * 64 + nt * 8 + (lane & 3) * 2;
            size_t b0 = ((size_t)w * NA_ + col) * HW_ + s0 + row;
            g_P[b0] = acc[mb][nt][0];
            g_P[b0 + HW_] = acc[mb][nt][1];
            g_P[b0 + 8] = acc[mb][nt][2];
            g_P[b0 + HW_ + 8] = acc[mb][nt][3];
        }
}

// ------------------------- K6: row softmax over s + fp16 out ---------------
__global__ __launch_bounds__(256) void softmax_rows() {
    int wid = threadIdx.x >> 5, lane = threadIdx.x & 31;
    size_t row = (size_t)blockIdx.x * 8 + wid;  // 0..32767
    const float* base = g_P + row * HW_;
    float4 a = *reinterpret_cast<const float4*>(base + lane * 8);
    float4 b = *reinterpret_cast<const float4*>(base + lane * 8 + 4);
    float m = fmaxf(fmaxf(fmaxf(a.x, a.y), fmaxf(a.z, a.w)),
                    fmaxf(fmaxf(b.x, b.y), fmaxf(b.z, b.w)));
#pragma unroll
    for (int o = 16; o; o >>= 1) m = fmaxf(m, __shfl_xor_sync(0xffffffffu, m, o));
    float e[8];
    e[0] = expf(a.x - m); e[1] = expf(a.y - m); e[2] = expf(a.z - m); e[3] = expf(a.w - m);
    e[4] = expf(b.x - m); e[5] = expf(b.y - m); e[6] = expf(b.z - m); e[7] = expf(b.w - m);
    float s = ((e[0] + e[1]) + (e[2] + e[3])) + ((e[4] + e[5]) + (e[6] + e[7]));
#pragma unroll
    for (int o = 16; o; o >>= 1) s += __shfl_xor_sync(0xffffffffu, s, o);
    float inv = 1.0f / s;
    __half h8[8];
#pragma unroll
    for (int i = 0; i < 8; ++i) h8[i] = __float2half(e[i] * inv);
    *reinterpret_cast<uint4*>(g_Pt + row * HW_ + lane * 8) = *reinterpret_cast<uint4*>(h8);
}

// ------------------------- K7: rewards + V0 init + int-sum center ---------
__global__ __launch_bounds__(256) void init_kernel(const float* __restrict__ inputs) {
    __shared__ int parti[8];
    int row = blockIdx.x, t = threadIdx.x;
    int wid = t >> 5, lane = t & 31;
    // zero slots 1..15 (replay-safe); first 15 blocks each zero one slot
    if (row < 15) {
        g_slot[row + 1][t] = 0;
        g_slot[row + 1][t + 256] = 0;
    }
    float v = inputs[row * 257 + t];
    g_R[row * HW_ + t] = v;
    g_V[row * HW_ + t] = v;
    int q = __float2int_rn(v * 4096.0f);
#pragma unroll
    for (int o = 16; o; o >>= 1) q += __shfl_xor_sync(0xffffffffu, q, o);
    if (lane == 0) parti[wid] = q;
    __syncthreads();
    int tot = ((parti[0] + parti[1]) + (parti[2] + parti[3])) +
              ((parti[4] + parti[5]) + (parti[6] + parti[7]));
    if (t == 0) g_slot[0][row] = tot;
    float mu = (float)tot * MUSC_;
    g_Wq[0][row * HW_ + t] = __float2half(v - mu);
}

// ------------------------- K8: Bellman + self-centering epilogue -----------
// reads g_Wq[it&1], writes g_Wq[(it+1)&1] (ping-pong kills the WAR race)
#define POFF_   65536
#define BSMEM_  98304

__global__ __launch_bounds__(256, 1) void bellman_h(int it) {
    extern __shared__ char smem[];
    __shared__ float red_s[8][32];
    uint32_t sb = smem_u32(smem);
    int tid = threadIdx.x, wid = tid >> 5, lane = tid & 31;
    int rb = blockIdx.x * 128;
    int w = blockIdx.y;
    int wr = wid >> 1, wc = wid & 1;

    const char* wsrc = (const char*)(g_Wq[it & 1] + (size_t)rb * 256);
    const char* pbase = (const char*)g_Pt + (size_t)w * 65536;

#pragma unroll
    for (int c = 0; c < 4; ++c) load_tile_g(sb + c * TILE16, wsrc + c * 128, 512, tid);
    load_tile_g(sb + POFF_, pbase, 512, tid);
    CP_COMMIT();
    load_tile_g(sb + POFF_ + TILE16, pbase + 128, 512, tid);
    CP_COMMIT();

    float acc[2][8][4];
#pragma unroll
    for (int mb = 0; mb < 2; ++mb)
#pragma unroll
        for (int nt = 0; nt < 8; ++nt)
#pragma unroll
            for (int q = 0; q < 4; ++q) acc[mb][nt][q] = 0.0f;

#pragma unroll
    for (int i = 0; i < 4; ++i) {
        if (i < 3)
            asm volatile("cp.async.wait_group 1;" ::: "memory");
        else
            asm volatile("cp.async.wait_group 0;" ::: "memory");
        __syncthreads();

        uint32_t vT = sb + i * TILE16;
        uint32_t pT = sb + POFF_ + (i & 1) * TILE16;

#pragma unroll
        for (int kk = 0; kk < 4; ++kk) {
            uint32_t ah[2][4];
#pragma unroll
            for (int mb = 0; mb < 2; ++mb) {
                int r = wr * 32 + mb * 16 + (lane & 15);
                int c16 = (lane >> 4) + kk * 2;
                ldsm_x4(ah[mb], sw_addr(vT, r, c16));
            }
            uint32_t bh[8][2];
#pragma unroll
            for (int np = 0; np < 4; ++np) {
                int n = wc * 64 + np * 16 + ((lane >> 4) << 3) + (lane & 7);
                int c16 = ((lane >> 3) & 1) + kk * 2;
                uint32_t r4[4];
                ldsm_x4(r4, sw_addr(pT, n, c16));
                bh[np * 2][0] = r4[0]; bh[np * 2][1] = r4[1];
                bh[np * 2 + 1][0] = r4[2]; bh[np * 2 + 1][1] = r4[3];
            }
#pragma unroll
            for (int mb = 0; mb < 2; ++mb)
#pragma unroll
                for (int nt = 0; nt < 8; ++nt) mma16816h(acc[mb][nt], ah[mb], bh[nt]);
        }
        __syncthreads();

        if (i < 2) {
            load_tile_g(sb + POFF_ + (i & 1) * TILE16, pbase + (i + 2) * 128, 512, tid);
            CP_COMMIT();
        }
    }

    int g = lane >> 2;
#pragma unroll
    for (int mb = 0; mb < 2; ++mb) {
        float mA = -1e30f, mB = -1e30f;
#pragma unroll
        for (int nt = 0; nt < 8; ++nt) {
            mA = fmaxf(mA, fmaxf(acc[mb][nt][0], acc[mb][nt][1]));
            mB = fmaxf(mB, fmaxf(acc[mb][nt][2], acc[mb][nt][3]));
        }
        mA = fmaxf(mA, __shfl_xor_sync(0xffffffffu, mA, 1));
        mA = fmaxf(mA, __shfl_xor_sync(0xffffffffu, mA, 2));
        mB = fmaxf(mB, __shfl_xor_sync(0xffffffffu, mB, 1));
        mB = fmaxf(mB, __shfl_xor_sync(0xffffffffu, mB, 2));
        if ((lane & 3) == 0) {
            red_s[wid][mb * 16 + g] = mA;
            red_s[wid][mb * 16 + 8 + g] = mB;
        }
    }
    __syncthreads();
    if (tid < 128) {
        int wrr = tid >> 5, rl = tid & 31;
        float m = fmaxf(red_s[wrr * 2][rl], red_s[wrr * 2 + 1][rl]);
        int row = rb + tid;
        // add-back = centering constant used by the writer of current Wq:
        //   init (it==0): mean(slot[0]);  iter it-1 (it>=1): mean(slot[it-1])
        int ait = it > 0 ? it - 1 : 0;
        float A = (float)g_slot[ait][row] * MUSC_;
        float v = g_R[row * HW_ + w] + m + A;
        g_V[row * HW_ + w] = v;
        if (it < 14) {
            // center new V with freshest complete mean: mean(slot[it]) = mu(V^it)
            float C = (float)g_slot[it][row] * MUSC_;
            g_Wq[(it + 1) & 1][row * HW_ + w] = __float2half(v - C);
            atomicAdd(&g_slot[it + 1][row], __float2int_rn(v * 4096.0f));
        }
    }
}

// ------------------------- K9: output assembly -----------------------------
__global__ void assemble_kernel(const float* __restrict__ rnn_hxs, float* __restrict__ out,
                                int out_size) {
    int idx = blockIdx.x * blockDim.x + threadIdx.x;
    if (idx >= out_size || idx >= OUTT_) return;
    int row, c;
    if (idx < OUT1_) {
        row = idx / HX_;
        c = idx - row * HX_;
    } else {
        int k = idx - OUT1_;
        int r2 = k / HX_;
        c = k - r2 * HX_;
        row = 448 + r2;
    }
    float v = (c < PASS_) ? rnn_hxs[row * HX_ + c] : g_V[row * HW_ + (c - PASS_)];
    out[idx] = v;
}

// ------------------------- launcher ----------------------------------------
extern "C" void kernel_launch(void* const* d_in, const int* in_sizes, int n_in,
                              void* d_out, int out_size) {
    const float* inputs = (const float*)d_in[0];
    const float* rnn_hxs = (const float*)d_in[1];
    const float* S = (const float*)d_in[2];
    const float* A = (const float*)d_in[3];
    const float* w_ih = (const float*)d_in[4];
    const float* w_hh = (const float*)d_in[5];
    const float* b_ih = (const float*)d_in[6];
    const float* b_hh = (const float*)d_in[7];
    const float* W1 = (const float*)d_in[8];
    const float* b1 = (const float*)d_in[9];
    const float* W2 = (const float*)d_in[10];
    const float* b2 = (const float*)d_in[11];
    float* out = (float*)d_out;

    cudaFuncSetAttribute(bellman_h, cudaFuncAttributeMaxDynamicSharedMemorySize, BSMEM_);
    cudaFuncSetAttribute(logits_mma, cudaFuncAttributeMaxDynamicSharedMemorySize, 131072);
    cudaFuncSetAttribute(mlp_mma, cudaFuncAttributeMaxDynamicSharedMemorySize, 131072);

    // fork a side stream (created per call; intentionally not destroyed — a
    // stream referenced by an in-progress capture must outlive the capture).
    cudaStream_t s2;
    cudaEvent_t evFork, evJoin;
    cudaStreamCreateWithFlags(&s2, cudaStreamNonBlocking);
    cudaEventCreateWithFlags(&evFork, cudaEventDisableTiming);
    cudaEventCreateWithFlags(&evJoin, cudaEventDisableTiming);

    cudaEventRecord(evFork, 0);
    cudaStreamWaitEvent(s2, evFork, 0);

    // branch A (legacy stream): GRU chain (single-SM, long)
    gi_kernel<<<HW_, 384>>>(S, w_ih, b_ih);
    gru_kernel<<<1, 384>>>(w_hh, b_hh);

    // branch B (side stream): MLP chain + init (independent of GRU)
    wsplit_kernel<<<2, 256, 0, s2>>>(W1, W2);
    xprep_kernel<<<dim3(HW_, 8), 256, 0, s2>>>(A, S);
    mlp_mma<<<256, 256, 131072, s2>>>(0, b1);
    mlp_mma<<<256, 256, 131072, s2>>>(1, b2);
    init_kernel<<<ROWS_, 256, 0, s2>>>(inputs);

    cudaEventRecord(evJoin, s2);
    cudaStreamWaitEvent(0, evJoin, 0);

    // joined: logits needs K (branch A) and Y2 (branch B)
    logits_mma<<<dim3(2, HW_), 256, 131072>>>();
    softmax_rows<<<HW_ * NA_ / 8, 256>>>();
    for (int it = 0; it < 15; ++it) {
        bellman_h<<<dim3(4, HW_), 256, BSMEM_>>>(it);
    }
    int total = out_size < OUTT_ ? out_size : OUTT_;
    assemble_kernel<<<(total + 255) / 256, 256>>>(rnn_hxs, out, out_size);
}

// round 17
// speedup vs baseline: 1.7231x; 1.1876x over previous
#include <cuda_runtime.h>
#include <cuda_bf16.h>
#include <cuda_fp16.h>
#include <math.h>
#include <stdint.h>

// Problem constants
#define T_      8
#define N_      64
#define HW_     256
#define HID_    128
#define NA_     128
#define HX_     514
#define PASS_   258
#define ROWS_   512
#define OUT1_   263168
#define OUTT_   296064

#define MUSC_   (1.0f / (4096.0f * 256.0f))

typedef unsigned long long ull;

// ------------------------- scratch (device globals; no allocs) -------------
__device__ float g_gi[HW_ * 384];
__device__ __nv_bfloat16 g_Kh[HW_ * HID_];
__device__ __nv_bfloat16 g_Kl[HW_ * HID_];
__device__ __nv_bfloat16 g_Xh[HW_ * NA_ * HID_];   // X = A+S, bf16 hi/lo
__device__ __nv_bfloat16 g_Xl[HW_ * NA_ * HID_];
__device__ __nv_bfloat16 g_Y1h[HW_ * NA_ * HID_];
__device__ __nv_bfloat16 g_Y1l[HW_ * NA_ * HID_];
__device__ __nv_bfloat16 g_Y2h[HW_ * NA_ * HID_];
__device__ __nv_bfloat16 g_Y2l[HW_ * NA_ * HID_];
__device__ __nv_bfloat16 g_W1h[HID_ * HID_];
__device__ __nv_bfloat16 g_W1l[HID_ * HID_];
__device__ __nv_bfloat16 g_W2h[HID_ * HID_];
__device__ __nv_bfloat16 g_W2l[HID_ * HID_];
__device__ float g_P[(size_t)HW_ * NA_ * HW_];    // logits, layout [w][a][s] fp32
__device__ __half g_Pt[(size_t)HW_ * NA_ * HW_];  // [w][a][s] fp16
__device__ float g_R[ROWS_ * HW_];
__device__ float g_V[ROWS_ * HW_];                // fp32 values
__device__ __half g_Wq[2][ROWS_ * HW_];           // fp16 centered values (ping-pong)
__device__ int g_slot[16][ROWS_];                 // int row-sums of V per iteration

// ------------------------- ptx helpers -------------------------------------
__device__ __forceinline__ void fma2(ull& d, ull a, ull b) {
    asm("fma.rn.f32x2 %0, %1, %2, %0;" : "+l"(d) : "l"(a), "l"(b));
}
__device__ __forceinline__ float2 unpack2(ull u) {
    float2 f;
    asm("mov.b64 {%0, %1}, %2;" : "=f"(f.x), "=f"(f.y) : "l"(u));
    return f;
}
__device__ __forceinline__ ull pack2(float x, float y) {
    ull u;
    asm("mov.b64 %0, {%1, %2};" : "=l"(u) : "f"(x), "f"(y));
    return u;
}
__device__ __forceinline__ uint32_t smem_u32(const void* p) {
    uint32_t a;
    asm("{ .reg .u64 t; cvta.to.shared.u64 t, %1; cvt.u32.u64 %0, t; }" : "=r"(a) : "l"(p));
    return a;
}
__device__ __forceinline__ void cp_async16(uint32_t dst, const void* src) {
    asm volatile("cp.async.cg.shared.global [%0], [%1], 16;" ::"r"(dst), "l"(src) : "memory");
}
#define CP_COMMIT() asm volatile("cp.async.commit_group;" ::: "memory")

__device__ __forceinline__ void ldsm_x4(uint32_t* r, uint32_t addr) {
    asm volatile("ldmatrix.sync.aligned.m8n8.x4.shared.b16 {%0,%1,%2,%3}, [%4];"
                 : "=r"(r[0]), "=r"(r[1]), "=r"(r[2]), "=r"(r[3]) : "r"(addr));
}
__device__ __forceinline__ void mma16816(float* c, const uint32_t* a, const uint32_t* b) {
    asm volatile(
        "mma.sync.aligned.m16n8k16.row.col.f32.bf16.bf16.f32 "
        "{%0,%1,%2,%3}, {%4,%5,%6,%7}, {%8,%9}, {%0,%1,%2,%3};"
        : "+f"(c[0]), "+f"(c[1]), "+f"(c[2]), "+f"(c[3])
        : "r"(a[0]), "r"(a[1]), "r"(a[2]), "r"(a[3]), "r"(b[0]), "r"(b[1]));
}
__device__ __forceinline__ void mma16816h(float* c, const uint32_t* a, const uint32_t* b) {
    asm volatile(
        "mma.sync.aligned.m16n8k16.row.col.f32.f16.f16.f32 "
        "{%0,%1,%2,%3}, {%4,%5,%6,%7}, {%8,%9}, {%0,%1,%2,%3};"
        : "+f"(c[0]), "+f"(c[1]), "+f"(c[2]), "+f"(c[3])
        : "r"(a[0]), "r"(a[1]), "r"(a[2]), "r"(a[3]), "r"(b[0]), "r"(b[1]));
}

// swizzled 16KB tile: 128 rows x 128B, seg16 c in 0..7: addr = r*128 + ((c ^ (r&7))<<4)
#define TILE16 16384
__device__ __forceinline__ uint32_t sw_addr(uint32_t base, int r, int c16) {
    return base + r * 128 + (((uint32_t)(c16 ^ (r & 7))) << 4);
}
// bf16 tile loader: 128 rows x 64 elems, stride in elements
__device__ __forceinline__ void load_tile_sw(uint32_t dst, const __nv_bfloat16* src, int stride,
                                             int tid) {
#pragma unroll
    for (int i = 0; i < 4; ++i) {
        int lin = tid + i * 256;
        int r = lin >> 3, seg = lin & 7;
        cp_async16(sw_addr(dst, r, seg), src + (size_t)r * stride + seg * 8);
    }
}
// generic byte-based tile loader: 128 rows x 128B per row from rowBytes-strided src
__device__ __forceinline__ void load_tile_g(uint32_t dst, const void* src, int rowBytes, int tid) {
    const char* s = (const char*)src;
#pragma unroll
    for (int i = 0; i < 4; ++i) {
        int lin = tid + i * 256;
        int r = lin >> 3, seg = lin & 7;
        cp_async16(sw_addr(dst, r, seg), s + (size_t)r * rowBytes + seg * 16);
    }
}

// ------------------------- K1: gi ------------------------------------------
__global__ void gi_kernel(const float* __restrict__ S, const float* __restrict__ w_ih,
                          const float* __restrict__ b_ih) {
    __shared__ float Ss[HID_];
    int blk = blockIdx.x;
    int o = threadIdx.x;
    if (o < HID_) Ss[o] = S[blk * HID_ + o];
    __syncthreads();
    float acc = b_ih[o];
#pragma unroll 8
    for (int k = 0; k < HID_; k += 4) {
        float4 w = *reinterpret_cast<const float4*>(&w_ih[o * HID_ + k]);
        acc += Ss[k] * w.x + Ss[k + 1] * w.y + Ss[k + 2] * w.z + Ss[k + 3] * w.w;
    }
    g_gi[blk * 384 + o] = acc;
}

// ------------------------- K2: GRU (register weights, ILP4) ----------------
__global__ __launch_bounds__(384, 1) void gru_kernel(const float* __restrict__ w_hh,
                                                     const float* __restrict__ b_hh) {
    __shared__ __align__(16) float hs[HID_];
    __shared__ float ghs[384];
    int o = threadIdx.x;

    ull w2[64];
#pragma unroll
    for (int i = 0; i < 64; ++i) {
        float2 v = reinterpret_cast<const float2*>(w_hh)[o * 64 + i];
        w2[i] = pack2(v.x, v.y);
    }
    if (o < HID_) hs[o] = 0.0f;
    float bh = b_hh[o];
    __syncthreads();

    for (int t = 0; t < HW_; ++t) {
        ull z = pack2(0.0f, 0.0f);
        ull a0 = pack2(bh, 0.0f), a1 = z, a2 = z, a3 = z;
        const ull* h2 = reinterpret_cast<const ull*>(hs);
#pragma unroll
        for (int i = 0; i < 64; i += 4) {
            fma2(a0, h2[i], w2[i]);
            fma2(a1, h2[i + 1], w2[i + 1]);
            fma2(a2, h2[i + 2], w2[i + 2]);
            fma2(a3, h2[i + 3], w2[i + 3]);
        }
        float2 p0 = unpack2(a0), p1 = unpack2(a1), p2 = unpack2(a2), p3 = unpack2(a3);
        ghs[o] = (p0.x + p0.y) + (p1.x + p1.y) + ((p2.x + p2.y) + (p3.x + p3.y));
        __syncthreads();
        if (o < HID_) {
            float gir = g_gi[t * 384 + o];
            float giz = g_gi[t * 384 + 128 + o];
            float gin = g_gi[t * 384 + 256 + o];
            float r = 1.0f / (1.0f + expf(-(gir + ghs[o])));
            float zz = 1.0f / (1.0f + expf(-(giz + ghs[o + 128])));
            float n = tanhf(gin + r * ghs[o + 256]);
            float hn = (1.0f - zz) * n + zz * hs[o];
            hs[o] = hn;
            __nv_bfloat16 hi = __float2bfloat16(hn);
            g_Kh[t * HID_ + o] = hi;
            g_Kl[t * HID_ + o] = __float2bfloat16(hn - __bfloat162float(hi));
        }
        __syncthreads();
    }
}

// ------------------------- K3a: split W1, W2 -------------------------------
__global__ void wsplit_kernel(const float* __restrict__ W1, const float* __restrict__ W2) {
    const float* src = blockIdx.x ? W2 : W1;
    __nv_bfloat16* dh = blockIdx.x ? g_W2h : g_W1h;
    __nv_bfloat16* dl = blockIdx.x ? g_W2l : g_W1l;
    for (int i = threadIdx.x; i < HID_ * HID_; i += blockDim.x) {
        float v = src[i];
        __nv_bfloat16 hi = __float2bfloat16(v);
        dh[i] = hi;
        dl[i] = __float2bfloat16(v - __bfloat162float(hi));
    }
}

// ------------------------- K3b: X = A + S, bf16 split ----------------------
__global__ __launch_bounds__(256) void xprep_kernel(const float* __restrict__ A,
                                                    const float* __restrict__ S) {
    int w = blockIdx.x, ab = blockIdx.y;
    int al = threadIdx.x >> 4, k8 = (threadIdx.x & 15) * 8;
    int a = ab * 16 + al;
    float4 a0 = *reinterpret_cast<const float4*>(&A[a * HID_ + k8]);
    float4 a1 = *reinterpret_cast<const float4*>(&A[a * HID_ + k8 + 4]);
    float4 s0 = *reinterpret_cast<const float4*>(&S[w * HID_ + k8]);
    float4 s1 = *reinterpret_cast<const float4*>(&S[w * HID_ + k8 + 4]);
    float v[8] = {a0.x + s0.x, a0.y + s0.y, a0.z + s0.z, a0.w + s0.w,
                  a1.x + s1.x, a1.y + s1.y, a1.z + s1.z, a1.w + s1.w};
    __nv_bfloat16 h8[8], l8[8];
#pragma unroll
    for (int i = 0; i < 8; ++i) {
        h8[i] = __float2bfloat16(v[i]);
        l8[i] = __float2bfloat16(v[i] - __bfloat162float(h8[i]));
    }
    size_t off = ((size_t)w * NA_ + a) * HID_ + k8;
    *reinterpret_cast<uint4*>(&g_Xh[off]) = *reinterpret_cast<uint4*>(h8);
    *reinterpret_cast<uint4*>(&g_Xl[off]) = *reinterpret_cast<uint4*>(l8);
}

// ------------------------- K4: unified MLP layer via mma (bf16 3-prod) -----
__global__ __launch_bounds__(256, 1) void mlp_mma(int layer, const float* __restrict__ bias) {
    extern __shared__ char smem[];
    uint32_t sb = smem_u32(smem);
    int tid = threadIdx.x, wid = tid >> 5, lane = tid & 31;
    int rt = blockIdx.x;
    int wr = wid >> 1, wc = wid & 1;

    const __nv_bfloat16* xh = layer ? g_Y1h : g_Xh;
    const __nv_bfloat16* xl = layer ? g_Y1l : g_Xl;
    const __nv_bfloat16* wh = layer ? g_W2h : g_W1h;
    const __nv_bfloat16* wl = layer ? g_W2l : g_W1l;
    __nv_bfloat16* dh = layer ? g_Y2h : g_Y1h;
    __nv_bfloat16* dl = layer ? g_Y2l : g_Y1l;

#pragma unroll
    for (int c = 0; c < 2; ++c) {
        load_tile_sw(sb + (0 * 2 + c) * TILE16, xh + (size_t)rt * 16384 + c * 64, 128, tid);
        load_tile_sw(sb + (1 * 2 + c) * TILE16, xl + (size_t)rt * 16384 + c * 64, 128, tid);
        load_tile_sw(sb + (2 * 2 + c) * TILE16, wh + c * 64, 128, tid);
        load_tile_sw(sb + (3 * 2 + c) * TILE16, wl + c * 64, 128, tid);
    }
    CP_COMMIT();
    asm volatile("cp.async.wait_group 0;" ::: "memory");
    __syncthreads();

    float acc[2][8][4];
#pragma unroll
    for (int mb = 0; mb < 2; ++mb)
#pragma unroll
        for (int nt = 0; nt < 8; ++nt)
#pragma unroll
            for (int q = 0; q < 4; ++q) acc[mb][nt][q] = 0.0f;

#pragma unroll
    for (int c = 0; c < 2; ++c) {
        uint32_t ahT = sb + c * TILE16, alT = sb + (2 + c) * TILE16;
        uint32_t bhT = sb + (4 + c) * TILE16, blT = sb + (6 + c) * TILE16;
#pragma unroll
        for (int kk = 0; kk < 4; ++kk) {
            uint32_t ah[2][4], al[2][4];
#pragma unroll
            for (int mb = 0; mb < 2; ++mb) {
                int r = wr * 32 + mb * 16 + (lane & 15);
                int c16 = (lane >> 4) + kk * 2;
                ldsm_x4(ah[mb], sw_addr(ahT, r, c16));
                ldsm_x4(al[mb], sw_addr(alT, r, c16));
            }
            uint32_t bh[8][2], bl[8][2];
#pragma unroll
            for (int np = 0; np < 4; ++np) {
                int n = wc * 64 + np * 16 + ((lane >> 4) << 3) + (lane & 7);
                int c16 = ((lane >> 3) & 1) + kk * 2;
                uint32_t r4[4];
                ldsm_x4(r4, sw_addr(bhT, n, c16));
                bh[np * 2][0] = r4[0]; bh[np * 2][1] = r4[1];
                bh[np * 2 + 1][0] = r4[2]; bh[np * 2 + 1][1] = r4[3];
                ldsm_x4(r4, sw_addr(blT, n, c16));
                bl[np * 2][0] = r4[0]; bl[np * 2][1] = r4[1];
                bl[np * 2 + 1][0] = r4[2]; bl[np * 2 + 1][1] = r4[3];
            }
#pragma unroll
            for (int mb = 0; mb < 2; ++mb)
#pragma unroll
                for (int nt = 0; nt < 8; ++nt) {
                    mma16816(acc[mb][nt], ah[mb], bh[nt]);
                    mma16816(acc[mb][nt], ah[mb], bl[nt]);
                    mma16816(acc[mb][nt], al[mb], bh[nt]);
                }
        }
    }
    int g = lane >> 2;
#pragma unroll
    for (int mb = 0; mb < 2; ++mb)
#pragma unroll
        for (int nt = 0; nt < 8; ++nt) {
            int col = wc * 64 + nt * 8 + (lane & 3) * 2;
            float bb0 = bias[col], bb1 = bias[col + 1];
#pragma unroll
            for (int h = 0; h < 2; ++h) {
                int row = rt * 128 + wr * 32 + mb * 16 + g + h * 8;
                float o0 = fmaxf(acc[mb][nt][2 * h] + bb0, 0.0f);
                float o1 = fmaxf(acc[mb][nt][2 * h + 1] + bb1, 0.0f);
                __nv_bfloat16 h0 = __float2bfloat16(o0);
                __nv_bfloat16 h1 = __float2bfloat16(o1);
                __nv_bfloat162 hp, lp;
                hp.x = h0; hp.y = h1;
                lp.x = __float2bfloat16(o0 - __bfloat162float(h0));
                lp.y = __float2bfloat16(o1 - __bfloat162float(h1));
                *reinterpret_cast<__nv_bfloat162*>(&dh[(size_t)row * HID_ + col]) = hp;
                *reinterpret_cast<__nv_bfloat162*>(&dl[(size_t)row * HID_ + col]) = lp;
            }
        }
}

// ------------------------- K5: logits via mma.sync, writes [w][a][s] -------
__global__ __launch_bounds__(256, 1) void logits_mma() {
    extern __shared__ char smem[];
    uint32_t sb = smem_u32(smem);
    int tid = threadIdx.x, wid = tid >> 5, lane = tid & 31;
    int s0 = blockIdx.x * 128;
    int w = blockIdx.y;
    int wr = wid >> 1, wc = wid & 1;

#pragma unroll
    for (int c = 0; c < 2; ++c) {
        load_tile_sw(sb + (0 * 2 + c) * TILE16, g_Kh + (size_t)s0 * 128 + c * 64, 128, tid);
        load_tile_sw(sb + (1 * 2 + c) * TILE16, g_Kl + (size_t)s0 * 128 + c * 64, 128, tid);
        load_tile_sw(sb + (2 * 2 + c) * TILE16, g_Y2h + (size_t)w * 128 * 128 + c * 64, 128, tid);
        load_tile_sw(sb + (3 * 2 + c) * TILE16, g_Y2l + (size_t)w * 128 * 128 + c * 64, 128, tid);
    }
    CP_COMMIT();
    asm volatile("cp.async.wait_group 0;" ::: "memory");
    __syncthreads();

    float acc[2][8][4];
#pragma unroll
    for (int mb = 0; mb < 2; ++mb)
#pragma unroll
        for (int nt = 0; nt < 8; ++nt)
#pragma unroll
            for (int q = 0; q < 4; ++q) acc[mb][nt][q] = 0.0f;

#pragma unroll
    for (int c = 0; c < 2; ++c) {
        uint32_t ahT = sb + c * TILE16, alT = sb + (2 + c) * TILE16;
        uint32_t bhT = sb + (4 + c) * TILE16, blT = sb + (6 + c) * TILE16;
#pragma unroll
        for (int kk = 0; kk < 4; ++kk) {
            uint32_t ah[2][4], al[2][4];
#pragma unroll
            for (int mb = 0; mb < 2; ++mb) {
                int r = wr * 32 + mb * 16 + (lane & 15);
                int c16 = (lane >> 4) + kk * 2;
                ldsm_x4(ah[mb], sw_addr(ahT, r, c16));
                ldsm_x4(al[mb], sw_addr(alT, r, c16));
            }
            uint32_t bh[8][2], bl[8][2];
#pragma unroll
            for (int np = 0; np < 4; ++np) {
                int n = wc * 64 + np * 16 + ((lane >> 4) << 3) + (lane & 7);
                int c16 = ((lane >> 3) & 1) + kk * 2;
                uint32_t r4[4];
                ldsm_x4(r4, sw_addr(bhT, n, c16));
                bh[np * 2][0] = r4[0]; bh[np * 2][1] = r4[1];
                bh[np * 2 + 1][0] = r4[2]; bh[np * 2 + 1][1] = r4[3];
                ldsm_x4(r4, sw_addr(blT, n, c16));
                bl[np * 2][0] = r4[0]; bl[np * 2][1] = r4[1];
                bl[np * 2 + 1][0] = r4[2]; bl[np * 2 + 1][1] = r4[3];
            }
#pragma unroll
            for (int mb = 0; mb < 2; ++mb)
#pragma unroll
                for (int nt = 0; nt < 8; ++nt) {
                    mma16816(acc[mb][nt], ah[mb], bh[nt]);
                    mma16816(acc[mb][nt], ah[mb], bl[nt]);
                    mma16816(acc[mb][nt], al[mb], bh[nt]);
                }
        }
    }
    // transposed store: L[w][a=col][s=s0+row]
    int g = lane >> 2;
#pragma unroll
    for (int mb = 0; mb < 2; ++mb)
#pragma unroll
        for (int nt = 0; nt < 8; ++nt) {
            int row = wr * 32 + mb * 16 + g;
            int col = wc * 64 + nt * 8 + (lane & 3) * 2;
            size_t b0 = ((size_t)w * NA_ + col) * HW_ + s0 + row;
            g_P[b0] = acc[mb][nt][0];
            g_P[b0 + HW_] = acc[mb][nt][1];
            g_P[b0 + 8] = acc[mb][nt][2];
            g_P[b0 + HW_ + 8] = acc[mb][nt][3];
        }
}

// ------------------------- K6: row softmax over s + fp16 out ---------------
__global__ __launch_bounds__(256) void softmax_rows() {
    int wid = threadIdx.x >> 5, lane = threadIdx.x & 31;
    size_t row = (size_t)blockIdx.x * 8 + wid;  // 0..32767
    const float* base = g_P + row * HW_;
    float4 a = *reinterpret_cast<const float4*>(base + lane * 8);
    float4 b = *reinterpret_cast<const float4*>(base + lane * 8 + 4);
    float m = fmaxf(fmaxf(fmaxf(a.x, a.y), fmaxf(a.z, a.w)),
                    fmaxf(fmaxf(b.x, b.y), fmaxf(b.z, b.w)));
#pragma unroll
    for (int o = 16; o; o >>= 1) m = fmaxf(m, __shfl_xor_sync(0xffffffffu, m, o));
    float e[8];
    e[0] = expf(a.x - m); e[1] = expf(a.y - m); e[2] = expf(a.z - m); e[3] = expf(a.w - m);
    e[4] = expf(b.x - m); e[5] = expf(b.y - m); e[6] = expf(b.z - m); e[7] = expf(b.w - m);
    float s = ((e[0] + e[1]) + (e[2] + e[3])) + ((e[4] + e[5]) + (e[6] + e[7]));
#pragma unroll
    for (int o = 16; o; o >>= 1) s += __shfl_xor_sync(0xffffffffu, s, o);
    float inv = 1.0f / s;
    __half h8[8];
#pragma unroll
    for (int i = 0; i < 8; ++i) h8[i] = __float2half(e[i] * inv);
    *reinterpret_cast<uint4*>(g_Pt + row * HW_ + lane * 8) = *reinterpret_cast<uint4*>(h8);
}

// ------------------------- K7: rewards + V0 init + int-sum center ---------
__global__ __launch_bounds__(256) void init_kernel(const float* __restrict__ inputs) {
    __shared__ int parti[8];
    int row = blockIdx.x, t = threadIdx.x;
    int wid = t >> 5, lane = t & 31;
    // zero slots 1..15 (replay-safe); first 15 blocks each zero one slot
    if (row < 15) {
        g_slot[row + 1][t] = 0;
        g_slot[row + 1][t + 256] = 0;
    }
    float v = inputs[row * 257 + t];
    g_R[row * HW_ + t] = v;
    g_V[row * HW_ + t] = v;
    int q = __float2int_rn(v * 4096.0f);
#pragma unroll
    for (int o = 16; o; o >>= 1) q += __shfl_xor_sync(0xffffffffu, q, o);
    if (lane == 0) parti[wid] = q;
    __syncthreads();
    int tot = ((parti[0] + parti[1]) + (parti[2] + parti[3])) +
              ((parti[4] + parti[5]) + (parti[6] + parti[7]));
    if (t == 0) g_slot[0][row] = tot;
    float mu = (float)tot * MUSC_;
    g_Wq[0][row * HW_ + t] = __float2half(v - mu);
}

// ------------------------- K8: Bellman + self-centering epilogue -----------
// reads g_Wq[it&1], writes g_Wq[(it+1)&1] (ping-pong kills the WAR race)
// __launch_bounds__(256, 2): cap regs at 128 so TWO CTAs fit per SM
// (2 x 96KB smem = 192KB <= 227KB); partner CTA fills sync/wait bubbles.
#define POFF_   65536
#define BSMEM_  98304

__global__ __launch_bounds__(256, 2) void bellman_h(int it) {
    extern __shared__ char smem[];
    __shared__ float red_s[8][32];
    uint32_t sb = smem_u32(smem);
    int tid = threadIdx.x, wid = tid >> 5, lane = tid & 31;
    int rb = blockIdx.x * 128;
    int w = blockIdx.y;
    int wr = wid >> 1, wc = wid & 1;

    const char* wsrc = (const char*)(g_Wq[it & 1] + (size_t)rb * 256);
    const char* pbase = (const char*)g_Pt + (size_t)w * 65536;

#pragma unroll
    for (int c = 0; c < 4; ++c) load_tile_g(sb + c * TILE16, wsrc + c * 128, 512, tid);
    load_tile_g(sb + POFF_, pbase, 512, tid);
    CP_COMMIT();
    load_tile_g(sb + POFF_ + TILE16, pbase + 128, 512, tid);
    CP_COMMIT();

    float acc[2][8][4];
#pragma unroll
    for (int mb = 0; mb < 2; ++mb)
#pragma unroll
        for (int nt = 0; nt < 8; ++nt)
#pragma unroll
            for (int q = 0; q < 4; ++q) acc[mb][nt][q] = 0.0f;

#pragma unroll
    for (int i = 0; i < 4; ++i) {
        if (i < 3)
            asm volatile("cp.async.wait_group 1;" ::: "memory");
        else
            asm volatile("cp.async.wait_group 0;" ::: "memory");
        __syncthreads();

        uint32_t vT = sb + i * TILE16;
        uint32_t pT = sb + POFF_ + (i & 1) * TILE16;

#pragma unroll
        for (int kk = 0; kk < 4; ++kk) {
            uint32_t ah[2][4];
#pragma unroll
            for (int mb = 0; mb < 2; ++mb) {
                int r = wr * 32 + mb * 16 + (lane & 15);
                int c16 = (lane >> 4) + kk * 2;
                ldsm_x4(ah[mb], sw_addr(vT, r, c16));
            }
            uint32_t bh[8][2];
#pragma unroll
            for (int np = 0; np < 4; ++np) {
                int n = wc * 64 + np * 16 + ((lane >> 4) << 3) + (lane & 7);
                int c16 = ((lane >> 3) & 1) + kk * 2;
                uint32_t r4[4];
                ldsm_x4(r4, sw_addr(pT, n, c16));
                bh[np * 2][0] = r4[0]; bh[np * 2][1] = r4[1];
                bh[np * 2 + 1][0] = r4[2]; bh[np * 2 + 1][1] = r4[3];
            }
#pragma unroll
            for (int mb = 0; mb < 2; ++mb)
#pragma unroll
                for (int nt = 0; nt < 8; ++nt) mma16816h(acc[mb][nt], ah[mb], bh[nt]);
        }
        __syncthreads();

        if (i < 2) {
            load_tile_g(sb + POFF_ + (i & 1) * TILE16, pbase + (i + 2) * 128, 512, tid);
            CP_COMMIT();
        }
    }

    int g = lane >> 2;
#pragma unroll
    for (int mb = 0; mb < 2; ++mb) {
        float mA = -1e30f, mB = -1e30f;
#pragma unroll
        for (int nt = 0; nt < 8; ++nt) {
            mA = fmaxf(mA, fmaxf(acc[mb][nt][0], acc[mb][nt][1]));
            mB = fmaxf(mB, fmaxf(acc[mb][nt][2], acc[mb][nt][3]));
        }
        mA = fmaxf(mA, __shfl_xor_sync(0xffffffffu, mA, 1));
        mA = fmaxf(mA, __shfl_xor_sync(0xffffffffu, mA, 2));
        mB = fmaxf(mB, __shfl_xor_sync(0xffffffffu, mB, 1));
        mB = fmaxf(mB, __shfl_xor_sync(0xffffffffu, mB, 2));
        if ((lane & 3) == 0) {
            red_s[wid][mb * 16 + g] = mA;
            red_s[wid][mb * 16 + 8 + g] = mB;
        }
    }
    __syncthreads();
    if (tid < 128) {
        int wrr = tid >> 5, rl = tid & 31;
        float m = fmaxf(red_s[wrr * 2][rl], red_s[wrr * 2 + 1][rl]);
        int row = rb + tid;
        // add-back = centering constant used by the writer of current Wq:
        //   init (it==0): mean(slot[0]);  iter it-1 (it>=1): mean(slot[it-1])
        int ait = it > 0 ? it - 1 : 0;
        float A = (float)g_slot[ait][row] * MUSC_;
        float v = g_R[row * HW_ + w] + m + A;
        g_V[row * HW_ + w] = v;
        if (it < 14) {
            // center new V with freshest complete mean: mean(slot[it]) = mu(V^it)
            float C = (float)g_slot[it][row] * MUSC_;
            g_Wq[(it + 1) & 1][row * HW_ + w] = __float2half(v - C);
            atomicAdd(&g_slot[it + 1][row], __float2int_rn(v * 4096.0f));
        }
    }
}

// ------------------------- K9: output assembly -----------------------------
__global__ void assemble_kernel(const float* __restrict__ rnn_hxs, float* __restrict__ out,
                                int out_size) {
    int idx = blockIdx.x * blockDim.x + threadIdx.x;
    if (idx >= out_size || idx >= OUTT_) return;
    int row, c;
    if (idx < OUT1_) {
        row = idx / HX_;
        c = idx - row * HX_;
    } else {
        int k = idx - OUT1_;
        int r2 = k / HX_;
        c = k - r2 * HX_;
        row = 448 + r2;
    }
    float v = (c < PASS_) ? rnn_hxs[row * HX_ + c] : g_V[row * HW_ + (c - PASS_)];
    out[idx] = v;
}

// ------------------------- launcher ----------------------------------------
extern "C" void kernel_launch(void* const* d_in, const int* in_sizes, int n_in,
                              void* d_out, int out_size) {
    const float* inputs = (const float*)d_in[0];
    const float* rnn_hxs = (const float*)d_in[1];
    const float* S = (const float*)d_in[2];
    const float* A = (const float*)d_in[3];
    const float* w_ih = (const float*)d_in[4];
    const float* w_hh = (const float*)d_in[5];
    const float* b_ih = (const float*)d_in[6];
    const float* b_hh = (const float*)d_in[7];
    const float* W1 = (const float*)d_in[8];
    const float* b1 = (const float*)d_in[9];
    const float* W2 = (const float*)d_in[10];
    const float* b2 = (const float*)d_in[11];
    float* out = (float*)d_out;

    cudaFuncSetAttribute(bellman_h, cudaFuncAttributeMaxDynamicSharedMemorySize, BSMEM_);
    cudaFuncSetAttribute(logits_mma, cudaFuncAttributeMaxDynamicSharedMemorySize, 131072);
    cudaFuncSetAttribute(mlp_mma, cudaFuncAttributeMaxDynamicSharedMemorySize, 131072);

    // fork a side stream (created per call; intentionally not destroyed — a
    // stream referenced by an in-progress capture must outlive the capture).
    cudaStream_t s2;
    cudaEvent_t evFork, evJoin;
    cudaStreamCreateWithFlags(&s2, cudaStreamNonBlocking);
    cudaEventCreateWithFlags(&evFork, cudaEventDisableTiming);
    cudaEventCreateWithFlags(&evJoin, cudaEventDisableTiming);

    cudaEventRecord(evFork, 0);
    cudaStreamWaitEvent(s2, evFork, 0);

    // branch A (legacy stream): GRU chain (single-SM, long)
    gi_kernel<<<HW_, 384>>>(S, w_ih, b_ih);
    gru_kernel<<<1, 384>>>(w_hh, b_hh);

    // branch B (side stream): MLP chain + init (independent of GRU)
    wsplit_kernel<<<2, 256, 0, s2>>>(W1, W2);
    xprep_kernel<<<dim3(HW_, 8), 256, 0, s2>>>(A, S);
    mlp_mma<<<256, 256, 131072, s2>>>(0, b1);
    mlp_mma<<<256, 256, 131072, s2>>>(1, b2);
    init_kernel<<<ROWS_, 256, 0, s2>>>(inputs);

    cudaEventRecord(evJoin, s2);
    cudaStreamWaitEvent(0, evJoin, 0);

    // joined: logits needs K (branch A) and Y2 (branch B)
    logits_mma<<<dim3(2, HW_), 256, 131072>>>();
    softmax_rows<<<HW_ * NA_ / 8, 256>>>();
    for (int it = 0; it < 15; ++it) {
        bellman_h<<<dim3(4, HW_), 256, BSMEM_>>>(it);
    }
    int total = out_size < OUTT_ ? out_size : OUTT_;
    assemble_kernel<<<(total + 255) / 256, 256>>>(rnn_hxs, out, out_size);
}